// round 10
// baseline (speedup 1.0000x reference)
#include <cuda_runtime.h>
#include <cuda_fp16.h>
#include <math.h>
#include <stdint.h>

// ---------------- problem constants ----------------
#define BATCH   32
#define HIMG    56
#define WIMG    56
#define CH      512
#define NHEAD   16
#define WS      7
#define SSH     3
#define HD      32
#define NWIN    49
#define NW_IMG  64
#define BN      (BATCH*NW_IMG)      // 2048 windows
#define MTOK    (BN*NWIN)           // 100352 tokens
#define HID     2048
#define SCALE   0.17677669529663687f
#define NN      (NWIN*NWIN)         // 2401

// ---------------- scratch ----------------
__device__ __align__(128) unsigned char g_R1[(size_t)MTOK * HID * 4];
__device__ __align__(128) unsigned char g_R2[(size_t)MTOK * CH * 2];

__device__ __align__(128) __half g_qkvT[3 * CH * CH];
__device__ __align__(128) __half g_projT[CH * CH];
__device__ __align__(128) __half g_fc1T[HID * CH];
__device__ __align__(128) __half g_fc2T[CH * HID];

// ---------------- helpers ----------------
__device__ __forceinline__ uint32_t smem_u32(const void* p) {
    uint32_t a;
    asm("{ .reg .u64 t; cvta.to.shared.u64 t, %1; cvt.u32.u64 %0, t; }" : "=r"(a) : "l"(p));
    return a;
}
#define CP16(dst, src) \
    asm volatile("cp.async.cg.shared.global [%0], [%1], 16;" :: "r"(dst), "l"(src))
#define CPCOMMIT() asm volatile("cp.async.commit_group;" ::: "memory")
#define CPWAIT1()  asm volatile("cp.async.wait_group 1;" ::: "memory")
#define CPWAIT0()  asm volatile("cp.async.wait_group 0;" ::: "memory")

#define LDSM4(r, a) \
    asm volatile("ldmatrix.sync.aligned.m8n8.x4.shared.b16 {%0,%1,%2,%3}, [%4];" \
        : "=r"((r)[0]), "=r"((r)[1]), "=r"((r)[2]), "=r"((r)[3]) : "r"(a))

__device__ __forceinline__ void mma_f16(float* c, const uint32_t* a, const uint32_t* b) {
    asm volatile("mma.sync.aligned.m16n8k16.row.col.f32.f16.f16.f32 "
        "{%0,%1,%2,%3}, {%4,%5,%6,%7}, {%8,%9}, {%0,%1,%2,%3};"
        : "+f"(c[0]), "+f"(c[1]), "+f"(c[2]), "+f"(c[3])
        : "r"(a[0]), "r"(a[1]), "r"(a[2]), "r"(a[3]), "r"(b[0]), "r"(b[1]));
}

// ---------------- weight transpose: W[K,N] -> Wt[N,K] fp16 ----------------
__global__ __launch_bounds__(256)
void wsplit_kernel(const float* __restrict__ W, __half* __restrict__ oh, int K, int N)
{
    __shared__ float t[32][33];
    int n0 = blockIdx.x * 32, k0 = blockIdx.y * 32;
    int tx = threadIdx.x & 31, ty = threadIdx.x >> 5;
    #pragma unroll
    for (int i = ty; i < 32; i += 8)
        t[i][tx] = W[(size_t)(k0 + i) * N + n0 + tx];
    __syncthreads();
    #pragma unroll
    for (int i = ty; i < 32; i += 8)
        oh[(size_t)(n0 + i) * K + k0 + tx] = __float2half_rn(t[tx][i]);
}

// ---------------- fused rel-pos bias + window mask table ----------------
__global__ __launch_bounds__(256)
void fusedbias_kernel(const float* __restrict__ table, const int* __restrict__ relidx,
                      const float* __restrict__ mask, float* __restrict__ fusedb)
{
    int wi = blockIdx.x >> 4, h = blockIdx.x & 15;
    float* dst = fusedb + (size_t)blockIdx.x * NN;
    const float* mrow = mask + (size_t)wi * NN;
    for (int i = threadIdx.x; i < NN; i += 256)
        dst[i] = table[relidx[i] * NHEAD + h] + mrow[i];
}

// ---------------- LayerNorm -> fp16 (mode1: shift+partition) ----------------
__global__ __launch_bounds__(128)
void ln_kernel(const float* __restrict__ x, const float* __restrict__ gamma,
               const float* __restrict__ beta, __half* __restrict__ oh, int mode)
{
    int tok = blockIdx.x;
    int src;
    if (mode == 1) {
        int w = tok / NWIN, n = tok - w * NWIN;
        int b = w >> 6, wi = w & 63;
        int wh = wi >> 3, ww = wi & 7;
        int i = n / WS, j = n - i * WS;
        int hp = wh * WS + i, wp = ww * WS + j;
        int hs = hp + SSH; if (hs >= HIMG) hs -= HIMG;
        int ws_ = wp + SSH; if (ws_ >= WIMG) ws_ -= WIMG;
        src = b * (HIMG * WIMG) + hs * WIMG + ws_;
    } else {
        src = tok;
    }
    int tid = threadIdx.x;
    int c = tid * 4;
    float4 v = *(const float4*)(x + (size_t)src * CH + c);
    float s  = v.x + v.y + v.z + v.w;
    float sq = v.x*v.x + v.y*v.y + v.z*v.z + v.w*v.w;
    #pragma unroll
    for (int off = 16; off; off >>= 1) {
        s  += __shfl_xor_sync(0xffffffffu, s, off);
        sq += __shfl_xor_sync(0xffffffffu, sq, off);
    }
    __shared__ float sh[8];
    int warp = tid >> 5, lane = tid & 31;
    if (lane == 0) { sh[warp] = s; sh[warp + 4] = sq; }
    __syncthreads();
    if (tid == 0) {
        float ts = sh[0] + sh[1] + sh[2] + sh[3];
        float tq = sh[4] + sh[5] + sh[6] + sh[7];
        float mean = ts * (1.0f / CH);
        float var = tq * (1.0f / CH) - mean * mean;
        sh[0] = mean; sh[1] = rsqrtf(var + 1e-5f);
    }
    __syncthreads();
    float mean = sh[0], inv = sh[1];
    float4 g4 = *(const float4*)(gamma + c);
    float4 b4 = *(const float4*)(beta + c);
    __half hh[4];
    hh[0] = __float2half_rn((v.x - mean) * inv * g4.x + b4.x);
    hh[1] = __float2half_rn((v.y - mean) * inv * g4.y + b4.y);
    hh[2] = __float2half_rn((v.z - mean) * inv * g4.z + b4.z);
    hh[3] = __float2half_rn((v.w - mean) * inv * g4.w + b4.w);
    *(uint2*)(oh + (size_t)tok * CH + c) = *(uint2*)hh;
}

// ---------------- fp16 GEMM: tile 256x128, 8 warps @ 64x64, K-chunk 64 ----------------
#define OFF_B   32768
#define STG_SZ  49152
#define TGEMM_SMEM (3 * STG_SZ)

template <int EPI>
__global__ void __launch_bounds__(256, 1)
tgemm(const __half* __restrict__ Ah, const __half* __restrict__ Bh,
      const float* __restrict__ bias, float* __restrict__ C,
      __half* __restrict__ Ch, int M, int N, int K)
{
    extern __shared__ __align__(128) char smem[];
    uint32_t sb = smem_u32(smem);
    int tid = threadIdx.x, wid = tid >> 5, lane = tid & 31;
    int m0 = blockIdx.y << 8, n0 = blockIdx.x << 7;
    int wm = wid & 3, wn = wid >> 2;

    // ---- loader coords ----
    // A: 256 rows x 128B -> 1 thread/row, 8x16B
    // B: 128 rows x 128B -> 2 threads/row, 4x16B
    int ar = tid;
    int br = tid >> 1, bc = (tid & 1) * 4;
    const char* gA = (const char*)(Ah + (size_t)(m0 + ar) * K);
    const char* gB = (const char*)(Bh + (size_t)(n0 + br) * K) + bc * 16;
    uint32_t swA[8], swB[4];
    #pragma unroll
    for (int j = 0; j < 8; ++j)
        swA[j] = (uint32_t)(ar * 128 + ((j ^ (ar & 7)) << 4));
    #pragma unroll
    for (int j = 0; j < 4; ++j)
        swB[j] = (uint32_t)(br * 128 + (((bc + j) ^ (br & 7)) << 4));

    // ---- ldmatrix coords ----
    int arow = wm * 64 + (lane & 15);
    uint32_t aterm = (uint32_t)(arow * 128);
    int axor = arow & 7;
    int ac16 = lane >> 4;
    int brow = wn * 64 + ((lane >> 4) & 1) * 8 + (lane & 7);
    uint32_t bterm = (uint32_t)(brow * 128);
    int bxor = brow & 7;
    int bc16 = (lane >> 3) & 1;

    float acc[4][8][4];
    #pragma unroll
    for (int i = 0; i < 4; ++i)
        #pragma unroll
        for (int j = 0; j < 8; ++j)
            #pragma unroll
            for (int q = 0; q < 4; ++q) acc[i][j][q] = 0.0f;

    const int nch = K >> 6;

    // prologue: issue chunks 0,1
    #pragma unroll
    for (int pc = 0; pc < 2; ++pc) {
        uint32_t s = sb + pc * STG_SZ;
        size_t go = (size_t)pc * 128;
        #pragma unroll
        for (int j = 0; j < 8; ++j) CP16(s + swA[j], gA + go + j * 16);
        #pragma unroll
        for (int j = 0; j < 4; ++j) CP16(s + OFF_B + swB[j], gB + go + j * 16);
        CPCOMMIT();
    }

    int buf = 0;
    for (int c = 0; c < nch; ++c) {
        if (c + 1 < nch) { CPWAIT1(); } else { CPWAIT0(); }
        __syncthreads();
        if (c + 2 < nch) {
            int b2 = buf + 2; if (b2 >= 3) b2 -= 3;
            uint32_t s = sb + b2 * STG_SZ;
            size_t go = (size_t)(c + 2) * 128;
            #pragma unroll
            for (int j = 0; j < 8; ++j) CP16(s + swA[j], gA + go + j * 16);
            #pragma unroll
            for (int j = 0; j < 4; ++j) CP16(s + OFF_B + swB[j], gB + go + j * 16);
            CPCOMMIT();
        } else {
            CPCOMMIT();
        }

        uint32_t sS = sb + buf * STG_SZ;
        #pragma unroll
        for (int k16 = 0; k16 < 4; ++k16) {
            uint32_t aoff = aterm + ((uint32_t)((2 * k16 + ac16) ^ axor) << 4);
            uint32_t boff = bterm + ((uint32_t)((2 * k16 + bc16) ^ bxor) << 4);
            uint32_t af[4][4], bf[4][4];
            #pragma unroll
            for (int f = 0; f < 4; ++f)
                LDSM4(af[f], sS + aoff + f * 2048);
            #pragma unroll
            for (int ng = 0; ng < 4; ++ng)
                LDSM4(bf[ng], sS + OFF_B + boff + ng * 2048);
            #pragma unroll
            for (int f = 0; f < 4; ++f)
                #pragma unroll
                for (int ng = 0; ng < 4; ++ng) {
                    mma_f16(acc[f][2 * ng],     af[f], &bf[ng][0]);
                    mma_f16(acc[f][2 * ng + 1], af[f], &bf[ng][2]);
                }
        }
        if (++buf == 3) buf = 0;
    }

    // ---- epilogue ----
    int r0 = m0 + wm * 64 + (lane >> 2);
    int cb = n0 + wn * 64 + (lane & 3) * 2;
    #pragma unroll
    for (int f = 0; f < 4; ++f) {
        #pragma unroll
        for (int n8 = 0; n8 < 8; ++n8) {
            int col = cb + n8 * 8;
            float2 bv = *(const float2*)(bias + col);
            #pragma unroll
            for (int rt = 0; rt < 2; ++rt) {
                int row = r0 + f * 16 + rt * 8;
                float vx = acc[f][n8][rt * 2]     + bv.x;
                float vy = acc[f][n8][rt * 2 + 1] + bv.y;
                if (EPI == 0) {
                    float2 r = {vx, vy};
                    *(float2*)(C + (size_t)row * N + col) = r;
                } else if (EPI == 1) {
                    float gx = 0.5f * vx * (1.0f + erff(vx * 0.70710678118654752f));
                    float gy = 0.5f * vy * (1.0f + erff(vy * 0.70710678118654752f));
                    __half hh[2];
                    hh[0] = __float2half_rn(gx);
                    hh[1] = __float2half_rn(gy);
                    *(uint32_t*)(Ch + (size_t)row * N + col) = *(uint32_t*)hh;
                } else if (EPI == 2) {
                    float* cp = C + (size_t)row * N + col;
                    float2 old = *(const float2*)cp;
                    float2 r = {vx + old.x, vy + old.y};
                    *(float2*)cp = r;
                } else {
                    __half hh[2];
                    hh[0] = __float2half_rn(vx);
                    hh[1] = __float2half_rn(vy);
                    *(uint32_t*)(Ch + (size_t)row * N + col) = *(uint32_t*)hh;
                }
            }
        }
    }
}

// ---------------- windowed attention (fp16 smem, 2x2 blocking) ----------------
#define QR 40
__global__ __launch_bounds__(256)
void attn_kernel(const __half* __restrict__ qkv, const float* __restrict__ fusedb,
                 __half* __restrict__ oh)
{
    __shared__ __half sq[50 * QR], sk[50 * QR], sv[50 * QR];
    __shared__ float ss[50 * 52];

    int bh = blockIdx.x;
    int b = bh >> 4, h = bh & 15;
    int tid = threadIdx.x;
    const float* fb = fusedb + (size_t)(((b & 63) << 4) + h) * NN;

    for (int idx = tid; idx < NWIN * 4; idx += 256) {
        int n = idx >> 2, d8 = (idx & 3) << 3;
        size_t base = (size_t)(b * NWIN + n) * (3 * CH) + h * HD + d8;
        *(uint4*)&sq[n * QR + d8] = *(const uint4*)(qkv + base);
        *(uint4*)&sk[n * QR + d8] = *(const uint4*)(qkv + base + CH);
        *(uint4*)&sv[n * QR + d8] = *(const uint4*)(qkv + base + 2 * CH);
    }
    __syncthreads();

    for (int idx = tid; idx < 625; idx += 256) {
        int np = idx / 25, mp = idx - np * 25;
        int n0 = np * 2, m0 = mp * 2;
        int n1 = n0 + 1, m1 = m0 + 1;
        float a00 = 0.f, a01 = 0.f, a10 = 0.f, a11 = 0.f;
        #pragma unroll
        for (int t = 0; t < 4; ++t) {
            union { uint4 u; __half2 hx[4]; } q0, q1, k0, k1;
            q0.u = *(const uint4*)&sq[n0 * QR + t * 8];
            q1.u = *(const uint4*)&sq[n1 * QR + t * 8];
            k0.u = *(const uint4*)&sk[m0 * QR + t * 8];
            k1.u = *(const uint4*)&sk[m1 * QR + t * 8];
            #pragma unroll
            for (int j = 0; j < 4; ++j) {
                float2 fq0 = __half22float2(q0.hx[j]);
                float2 fq1 = __half22float2(q1.hx[j]);
                float2 fk0 = __half22float2(k0.hx[j]);
                float2 fk1 = __half22float2(k1.hx[j]);
                a00 += fq0.x * fk0.x + fq0.y * fk0.y;
                a01 += fq0.x * fk1.x + fq0.y * fk1.y;
                a10 += fq1.x * fk0.x + fq1.y * fk0.y;
                a11 += fq1.x * fk1.x + fq1.y * fk1.y;
            }
        }
        bool nv = (n1 < NWIN), mv = (m1 < NWIN);
        ss[n0 * 52 + m0] = a00 * SCALE + fb[n0 * NWIN + m0];
        if (mv) ss[n0 * 52 + m1] = a01 * SCALE + fb[n0 * NWIN + m1];
        if (nv) {
            ss[n1 * 52 + m0] = a10 * SCALE + fb[n1 * NWIN + m0];
            if (mv) ss[n1 * 52 + m1] = a11 * SCALE + fb[n1 * NWIN + m1];
        }
    }
    __syncthreads();

    int warp = tid >> 5, lane = tid & 31;
    for (int r = warp; r < NWIN; r += 8) {
        float v1 = ss[r * 52 + lane];
        float v2 = (lane + 32 < NWIN) ? ss[r * 52 + lane + 32] : -1e30f;
        float mx = fmaxf(v1, v2);
        #pragma unroll
        for (int off = 16; off; off >>= 1)
            mx = fmaxf(mx, __shfl_xor_sync(0xffffffffu, mx, off));
        float e1 = expf(v1 - mx);
        float e2 = (lane + 32 < NWIN) ? expf(v2 - mx) : 0.0f;
        float sum = e1 + e2;
        #pragma unroll
        for (int off = 16; off; off >>= 1)
            sum += __shfl_xor_sync(0xffffffffu, sum, off);
        float inv = 1.0f / sum;
        ss[r * 52 + lane] = e1 * inv;
        if (lane + 32 < NWIN) ss[r * 52 + lane + 32] = e2 * inv;
    }
    __syncthreads();

    for (int idx = tid; idx < 400; idx += 256) {
        int np = idx >> 4, dp = idx & 15;
        int n0 = np * 2, n1 = n0 + 1, d = dp * 2;
        const float* p0 = &ss[n0 * 52];
        const float* p1 = &ss[n1 * 52];
        float ax0 = 0.f, ay0 = 0.f, ax1 = 0.f, ay1 = 0.f;
        #pragma unroll 7
        for (int m = 0; m < NWIN; ++m) {
            float2 vf = __half22float2(*(const __half2*)&sv[m * QR + d]);
            float b0 = p0[m], b1 = p1[m];
            ax0 += b0 * vf.x; ay0 += b0 * vf.y;
            ax1 += b1 * vf.x; ay1 += b1 * vf.y;
        }
        size_t ob = (size_t)(b * NWIN + n0) * CH + h * HD + d;
        *(__half2*)(oh + ob) = __floats2half2_rn(ax0, ay0);
        if (n1 < NWIN)
            *(__half2*)(oh + ob + CH) = __floats2half2_rn(ax1, ay1);
    }
}

// ---------------- fused: reverse+roll+residual -> out, then LN2 -> yh ----------------
__global__ __launch_bounds__(128)
void fuse2_kernel(const float* __restrict__ x, const float* __restrict__ proj,
                  const float* __restrict__ gamma, const float* __restrict__ beta,
                  float* __restrict__ out, __half* __restrict__ yh)
{
    int tok = blockIdx.x;
    int b = tok / (HIMG * WIMG);
    int rem = tok - b * (HIMG * WIMG);
    int hp0 = rem / WIMG, wp0 = rem - hp0 * WIMG;
    int hp = hp0 - SSH; if (hp < 0) hp += HIMG;
    int wp = wp0 - SSH; if (wp < 0) wp += WIMG;
    int wh = hp / WS, i = hp - wh * WS;
    int ww = wp / WS, j = wp - ww * WS;
    int src = (b * NW_IMG + wh * 8 + ww) * NWIN + i * WS + j;

    int tid = threadIdx.x;
    int c = tid * 4;
    float4 a = *(const float4*)(x + (size_t)tok * CH + c);
    float4 p = *(const float4*)(proj + (size_t)src * CH + c);
    a.x += p.x; a.y += p.y; a.z += p.z; a.w += p.w;
    *(float4*)(out + (size_t)tok * CH + c) = a;

    float s  = a.x + a.y + a.z + a.w;
    float sq = a.x*a.x + a.y*a.y + a.z*a.z + a.w*a.w;
    #pragma unroll
    for (int off = 16; off; off >>= 1) {
        s  += __shfl_xor_sync(0xffffffffu, s, off);
        sq += __shfl_xor_sync(0xffffffffu, sq, off);
    }
    __shared__ float sh[8];
    int warp = tid >> 5, lane = tid & 31;
    if (lane == 0) { sh[warp] = s; sh[warp + 4] = sq; }
    __syncthreads();
    if (tid == 0) {
        float ts = sh[0] + sh[1] + sh[2] + sh[3];
        float tq = sh[4] + sh[5] + sh[6] + sh[7];
        float mean = ts * (1.0f / CH);
        float var = tq * (1.0f / CH) - mean * mean;
        sh[0] = mean; sh[1] = rsqrtf(var + 1e-5f);
    }
    __syncthreads();
    float mean = sh[0], inv = sh[1];
    float4 g4 = *(const float4*)(gamma + c);
    float4 b4 = *(const float4*)(beta + c);
    __half hh[4];
    hh[0] = __float2half_rn((a.x - mean) * inv * g4.x + b4.x);
    hh[1] = __float2half_rn((a.y - mean) * inv * g4.y + b4.y);
    hh[2] = __float2half_rn((a.z - mean) * inv * g4.z + b4.z);
    hh[3] = __float2half_rn((a.w - mean) * inv * g4.w + b4.w);
    *(uint2*)(yh + (size_t)tok * CH + c) = *(uint2*)hh;
}

// ---------------- launcher ----------------
extern "C" void kernel_launch(void* const* d_in, const int* in_sizes, int n_in,
                              void* d_out, int out_size)
{
    const float* x        = (const float*)d_in[0];
    const float* norm1_g  = (const float*)d_in[1];
    const float* norm1_b  = (const float*)d_in[2];
    const float* qkv_w    = (const float*)d_in[3];
    const float* qkv_b    = (const float*)d_in[4];
    const float* rel_tab  = (const float*)d_in[5];
    const float* proj_w   = (const float*)d_in[6];
    const float* proj_b   = (const float*)d_in[7];
    const float* norm2_g  = (const float*)d_in[8];
    const float* norm2_b  = (const float*)d_in[9];
    const float* fc1_w    = (const float*)d_in[10];
    const float* fc1_b    = (const float*)d_in[11];
    const float* fc2_w    = (const float*)d_in[12];
    const float* fc2_b    = (const float*)d_in[13];
    const int*   rel_idx  = (const int*)d_in[14];
    const float* attn_msk = (const float*)d_in[15];
    float* out = (float*)d_out;

    unsigned char *R1, *R2;
    cudaGetSymbolAddress((void**)&R1, g_R1);
    cudaGetSymbolAddress((void**)&R2, g_R2);
    __half *qkvT, *projT, *fc1T, *fc2T;
    cudaGetSymbolAddress((void**)&qkvT, g_qkvT);
    cudaGetSymbolAddress((void**)&projT, g_projT);
    cudaGetSymbolAddress((void**)&fc1T, g_fc1T);
    cudaGetSymbolAddress((void**)&fc2T, g_fc2T);

    __half* qkv = (__half*)R1;
    float* proj = (float*)(R1 + (size_t)MTOK * 3 * CH * 2);
    float* fusedb = (float*)(R1 + (size_t)600 * 1024 * 1024);
    __half* hid = (__half*)R1;
    __half* act = (__half*)R2;

    cudaFuncSetAttribute(tgemm<0>, cudaFuncAttributeMaxDynamicSharedMemorySize, TGEMM_SMEM);
    cudaFuncSetAttribute(tgemm<1>, cudaFuncAttributeMaxDynamicSharedMemorySize, TGEMM_SMEM);
    cudaFuncSetAttribute(tgemm<2>, cudaFuncAttributeMaxDynamicSharedMemorySize, TGEMM_SMEM);
    cudaFuncSetAttribute(tgemm<3>, cudaFuncAttributeMaxDynamicSharedMemorySize, TGEMM_SMEM);

    // 0) weight transpose + fused bias table
    wsplit_kernel<<<dim3(3 * CH / 32, CH / 32), 256>>>(qkv_w,  qkvT, CH, 3 * CH);
    wsplit_kernel<<<dim3(CH / 32,     CH / 32), 256>>>(proj_w, projT, CH, CH);
    wsplit_kernel<<<dim3(HID / 32,    CH / 32), 256>>>(fc1_w,  fc1T, CH, HID);
    wsplit_kernel<<<dim3(CH / 32,    HID / 32), 256>>>(fc2_w,  fc2T, HID, CH);
    fusedbias_kernel<<<NW_IMG * NHEAD, 256>>>(rel_tab, rel_idx, attn_msk, fusedb);

    // 1) LN1 + shift + window partition
    ln_kernel<<<MTOK, 128>>>(x, norm1_g, norm1_b, act, 1);

    // 2) QKV GEMM -> fp16
    tgemm<3><<<dim3(3 * CH / 128, MTOK / 256), 256, TGEMM_SMEM>>>(
        act, qkvT, qkv_b, nullptr, qkv, MTOK, 3 * CH, CH);

    // 3) attention
    attn_kernel<<<BN * NHEAD, 256>>>(qkv, fusedb, act);

    // 4) proj GEMM -> fp32
    tgemm<0><<<dim3(CH / 128, MTOK / 256), 256, TGEMM_SMEM>>>(
        act, projT, proj_b, proj, nullptr, MTOK, CH, CH);

    // 5+6) reverse + residual -> d_out, fused LN2
    fuse2_kernel<<<MTOK, 128>>>(x, proj, norm2_g, norm2_b, out, act);

    // 7) FC1 + GELU -> fp16 hid
    tgemm<1><<<dim3(HID / 128, MTOK / 256), 256, TGEMM_SMEM>>>(
        act, fc1T, fc1_b, nullptr, hid, MTOK, HID, CH);

    // 8) FC2 + residual into d_out
    tgemm<2><<<dim3(CH / 128, MTOK / 256), 256, TGEMM_SMEM>>>(
        hid, fc2T, fc2_b, out, nullptr, MTOK, CH, HID);

    (void)in_sizes; (void)n_in; (void)out_size;
}

// round 11
// speedup vs baseline: 1.0103x; 1.0103x over previous
#include <cuda_runtime.h>
#include <cuda_fp16.h>
#include <math.h>
#include <stdint.h>

// ---------------- problem constants ----------------
#define BATCH   32
#define HIMG    56
#define WIMG    56
#define CH      512
#define NHEAD   16
#define WS      7
#define SSH     3
#define HD      32
#define NWIN    49
#define NW_IMG  64
#define BN      (BATCH*NW_IMG)      // 2048 windows
#define MTOK    (BN*NWIN)           // 100352 tokens
#define HID     2048
#define SCALE   0.17677669529663687f
#define NN      (NWIN*NWIN)         // 2401

// ---------------- scratch ----------------
__device__ __align__(128) unsigned char g_R1[(size_t)MTOK * HID * 4];
__device__ __align__(128) unsigned char g_R2[(size_t)MTOK * CH * 2];

__device__ __align__(128) __half g_qkvT[3 * CH * CH];
__device__ __align__(128) __half g_projT[CH * CH];
__device__ __align__(128) __half g_fc1T[HID * CH];
__device__ __align__(128) __half g_fc2T[CH * HID];

// ---------------- helpers ----------------
__device__ __forceinline__ uint32_t smem_u32(const void* p) {
    uint32_t a;
    asm("{ .reg .u64 t; cvta.to.shared.u64 t, %1; cvt.u32.u64 %0, t; }" : "=r"(a) : "l"(p));
    return a;
}
#define CP16(dst, src) \
    asm volatile("cp.async.cg.shared.global [%0], [%1], 16;" :: "r"(dst), "l"(src))
#define CPCOMMIT() asm volatile("cp.async.commit_group;" ::: "memory")
#define CPWAIT1()  asm volatile("cp.async.wait_group 1;" ::: "memory")
#define CPWAIT0()  asm volatile("cp.async.wait_group 0;" ::: "memory")

#define LDSM4(r, a) \
    asm volatile("ldmatrix.sync.aligned.m8n8.x4.shared.b16 {%0,%1,%2,%3}, [%4];" \
        : "=r"((r)[0]), "=r"((r)[1]), "=r"((r)[2]), "=r"((r)[3]) : "r"(a))

// fp16-accumulate mma: D(f16x4 in 2 regs) = A*B + C(f16)
__device__ __forceinline__ void mma_f16acc(uint32_t* c, const uint32_t* a, const uint32_t* b) {
    asm volatile("mma.sync.aligned.m16n8k16.row.col.f16.f16.f16.f16 "
        "{%0,%1}, {%2,%3,%4,%5}, {%6,%7}, {%0,%1};"
        : "+r"(c[0]), "+r"(c[1])
        : "r"(a[0]), "r"(a[1]), "r"(a[2]), "r"(a[3]), "r"(b[0]), "r"(b[1]));
}

// ---------------- weight transpose: W[K,N] -> Wt[N,K] fp16 ----------------
__global__ __launch_bounds__(256)
void wsplit_kernel(const float* __restrict__ W, __half* __restrict__ oh, int K, int N)
{
    __shared__ float t[32][33];
    int n0 = blockIdx.x * 32, k0 = blockIdx.y * 32;
    int tx = threadIdx.x & 31, ty = threadIdx.x >> 5;
    #pragma unroll
    for (int i = ty; i < 32; i += 8)
        t[i][tx] = W[(size_t)(k0 + i) * N + n0 + tx];
    __syncthreads();
    #pragma unroll
    for (int i = ty; i < 32; i += 8)
        oh[(size_t)(n0 + i) * K + k0 + tx] = __float2half_rn(t[tx][i]);
}

// ---------------- fused rel-pos bias + window mask table ----------------
__global__ __launch_bounds__(256)
void fusedbias_kernel(const float* __restrict__ table, const int* __restrict__ relidx,
                      const float* __restrict__ mask, float* __restrict__ fusedb)
{
    int wi = blockIdx.x >> 4, h = blockIdx.x & 15;
    float* dst = fusedb + (size_t)blockIdx.x * NN;
    const float* mrow = mask + (size_t)wi * NN;
    for (int i = threadIdx.x; i < NN; i += 256)
        dst[i] = table[relidx[i] * NHEAD + h] + mrow[i];
}

// ---------------- LayerNorm -> fp16 (mode1: shift+partition) ----------------
__global__ __launch_bounds__(128)
void ln_kernel(const float* __restrict__ x, const float* __restrict__ gamma,
               const float* __restrict__ beta, __half* __restrict__ oh, int mode)
{
    int tok = blockIdx.x;
    int src;
    if (mode == 1) {
        int w = tok / NWIN, n = tok - w * NWIN;
        int b = w >> 6, wi = w & 63;
        int wh = wi >> 3, ww = wi & 7;
        int i = n / WS, j = n - i * WS;
        int hp = wh * WS + i, wp = ww * WS + j;
        int hs = hp + SSH; if (hs >= HIMG) hs -= HIMG;
        int ws_ = wp + SSH; if (ws_ >= WIMG) ws_ -= WIMG;
        src = b * (HIMG * WIMG) + hs * WIMG + ws_;
    } else {
        src = tok;
    }
    int tid = threadIdx.x;
    int c = tid * 4;
    float4 v = *(const float4*)(x + (size_t)src * CH + c);
    float s  = v.x + v.y + v.z + v.w;
    float sq = v.x*v.x + v.y*v.y + v.z*v.z + v.w*v.w;
    #pragma unroll
    for (int off = 16; off; off >>= 1) {
        s  += __shfl_xor_sync(0xffffffffu, s, off);
        sq += __shfl_xor_sync(0xffffffffu, sq, off);
    }
    __shared__ float sh[8];
    int warp = tid >> 5, lane = tid & 31;
    if (lane == 0) { sh[warp] = s; sh[warp + 4] = sq; }
    __syncthreads();
    if (tid == 0) {
        float ts = sh[0] + sh[1] + sh[2] + sh[3];
        float tq = sh[4] + sh[5] + sh[6] + sh[7];
        float mean = ts * (1.0f / CH);
        float var = tq * (1.0f / CH) - mean * mean;
        sh[0] = mean; sh[1] = rsqrtf(var + 1e-5f);
    }
    __syncthreads();
    float mean = sh[0], inv = sh[1];
    float4 g4 = *(const float4*)(gamma + c);
    float4 b4 = *(const float4*)(beta + c);
    __half hh[4];
    hh[0] = __float2half_rn((v.x - mean) * inv * g4.x + b4.x);
    hh[1] = __float2half_rn((v.y - mean) * inv * g4.y + b4.y);
    hh[2] = __float2half_rn((v.z - mean) * inv * g4.z + b4.z);
    hh[3] = __float2half_rn((v.w - mean) * inv * g4.w + b4.w);
    *(uint2*)(oh + (size_t)tok * CH + c) = *(uint2*)hh;
}

// ---------------- fp16 GEMM (fp16 accumulate, fold to fp32 per K-chunk) ----------------
// Tile 128x128, 8 warps @ 32x64, K-chunk 64, 3 stages. R9 layout.
#define OFF_B   16384
#define STG_SZ  32768
#define TGEMM_SMEM (3 * STG_SZ)

template <int EPI>
__global__ void __launch_bounds__(256)
tgemm(const __half* __restrict__ Ah, const __half* __restrict__ Bh,
      const float* __restrict__ bias, float* __restrict__ C,
      __half* __restrict__ Ch, int M, int N, int K)
{
    extern __shared__ __align__(128) char smem[];
    uint32_t sb = smem_u32(smem);
    int tid = threadIdx.x, wid = tid >> 5, lane = tid & 31;
    int m0 = blockIdx.y << 7, n0 = blockIdx.x << 7;
    int wm = wid & 3, wn = wid >> 2;

    int ar = tid >> 1, ac = (tid & 1) * 4;
    const char* gA = (const char*)(Ah + (size_t)(m0 + ar) * K) + ac * 16;
    const char* gB = (const char*)(Bh + (size_t)(n0 + ar) * K) + ac * 16;
    uint32_t sw[4];
    #pragma unroll
    for (int j = 0; j < 4; ++j)
        sw[j] = (uint32_t)(ar * 128 + (((ac + j) ^ (ar & 7)) << 4));

    int arow = wm * 32 + (lane & 15);
    uint32_t aterm = (uint32_t)(arow * 128);
    int axor = arow & 7;
    int ac16 = lane >> 4;
    int brow = wn * 64 + ((lane >> 4) & 1) * 8 + (lane & 7);
    uint32_t bterm = (uint32_t)(brow * 128);
    int bxor = brow & 7;
    int bc16 = (lane >> 3) & 1;

    float accf[2][8][4];
    #pragma unroll
    for (int i = 0; i < 2; ++i)
        #pragma unroll
        for (int j = 0; j < 8; ++j)
            #pragma unroll
            for (int q = 0; q < 4; ++q) accf[i][j][q] = 0.0f;

    const int nch = K >> 6;

    #pragma unroll
    for (int pc = 0; pc < 2; ++pc) {
        uint32_t s = sb + pc * STG_SZ;
        size_t go = (size_t)pc * 128;
        #pragma unroll
        for (int j = 0; j < 4; ++j) {
            CP16(s + sw[j],         gA + go + j * 16);
            CP16(s + OFF_B + sw[j], gB + go + j * 16);
        }
        CPCOMMIT();
    }

    int buf = 0;
    for (int c = 0; c < nch; ++c) {
        if (c + 1 < nch) { CPWAIT1(); } else { CPWAIT0(); }
        __syncthreads();
        if (c + 2 < nch) {
            int b2 = buf + 2; if (b2 >= 3) b2 -= 3;
            uint32_t s = sb + b2 * STG_SZ;
            size_t go = (size_t)(c + 2) * 128;
            #pragma unroll
            for (int j = 0; j < 4; ++j) {
                CP16(s + sw[j],         gA + go + j * 16);
                CP16(s + OFF_B + sw[j], gB + go + j * 16);
            }
            CPCOMMIT();
        } else {
            CPCOMMIT();
        }

        // fp16 window accumulators for this K=64 chunk
        uint32_t a16[2][8][2];
        #pragma unroll
        for (int i = 0; i < 2; ++i)
            #pragma unroll
            for (int j = 0; j < 8; ++j) { a16[i][j][0] = 0u; a16[i][j][1] = 0u; }

        uint32_t sS = sb + buf * STG_SZ;
        #pragma unroll
        for (int k16 = 0; k16 < 4; ++k16) {
            uint32_t ah[2][4];
            uint32_t aoff = aterm + ((uint32_t)((2 * k16 + ac16) ^ axor) << 4);
            LDSM4(ah[0], sS + aoff);
            LDSM4(ah[1], sS + aoff + 2048);
            uint32_t boff = bterm + ((uint32_t)((2 * k16 + bc16) ^ bxor) << 4);
            #pragma unroll
            for (int ng = 0; ng < 4; ++ng) {
                uint32_t bh[4];
                LDSM4(bh, sS + OFF_B + boff + ng * 2048);
                #pragma unroll
                for (int mt = 0; mt < 2; ++mt) {
                    mma_f16acc(a16[mt][2 * ng],     ah[mt], &bh[0]);
                    mma_f16acc(a16[mt][2 * ng + 1], ah[mt], &bh[2]);
                }
            }
        }
        // fold fp16 window into fp32 accumulators
        #pragma unroll
        for (int mt = 0; mt < 2; ++mt)
            #pragma unroll
            for (int j = 0; j < 8; ++j) {
                float2 f0 = __half22float2(*(__half2*)&a16[mt][j][0]);
                float2 f1 = __half22float2(*(__half2*)&a16[mt][j][1]);
                accf[mt][j][0] += f0.x;
                accf[mt][j][1] += f0.y;
                accf[mt][j][2] += f1.x;
                accf[mt][j][3] += f1.y;
            }
        if (++buf == 3) buf = 0;
    }

    // ---- epilogue ----
    int r0 = m0 + wm * 32 + (lane >> 2);
    int cb = n0 + wn * 64 + (lane & 3) * 2;
    #pragma unroll
    for (int mt = 0; mt < 2; ++mt) {
        #pragma unroll
        for (int n8 = 0; n8 < 8; ++n8) {
            int col = cb + n8 * 8;
            float2 bv = *(const float2*)(bias + col);
            #pragma unroll
            for (int rt = 0; rt < 2; ++rt) {
                int row = r0 + mt * 16 + rt * 8;
                float vx = accf[mt][n8][rt * 2]     + bv.x;
                float vy = accf[mt][n8][rt * 2 + 1] + bv.y;
                if (EPI == 0) {
                    float2 r = {vx, vy};
                    *(float2*)(C + (size_t)row * N + col) = r;
                } else if (EPI == 1) {
                    float gx = 0.5f * vx * (1.0f + erff(vx * 0.70710678118654752f));
                    float gy = 0.5f * vy * (1.0f + erff(vy * 0.70710678118654752f));
                    __half hh[2];
                    hh[0] = __float2half_rn(gx);
                    hh[1] = __float2half_rn(gy);
                    *(uint32_t*)(Ch + (size_t)row * N + col) = *(uint32_t*)hh;
                } else if (EPI == 2) {
                    float* cp = C + (size_t)row * N + col;
                    float2 old = *(const float2*)cp;
                    float2 r = {vx + old.x, vy + old.y};
                    *(float2*)cp = r;
                } else {
                    __half hh[2];
                    hh[0] = __float2half_rn(vx);
                    hh[1] = __float2half_rn(vy);
                    *(uint32_t*)(Ch + (size_t)row * N + col) = *(uint32_t*)hh;
                }
            }
        }
    }
}

// ---------------- windowed attention (fp16 smem, 2x2 blocking) ----------------
#define QR 40
__global__ __launch_bounds__(256)
void attn_kernel(const __half* __restrict__ qkv, const float* __restrict__ fusedb,
                 __half* __restrict__ oh)
{
    __shared__ __half sq[50 * QR], sk[50 * QR], sv[50 * QR];
    __shared__ float ss[50 * 52];

    int bh = blockIdx.x;
    int b = bh >> 4, h = bh & 15;
    int tid = threadIdx.x;
    const float* fb = fusedb + (size_t)(((b & 63) << 4) + h) * NN;

    for (int idx = tid; idx < NWIN * 4; idx += 256) {
        int n = idx >> 2, d8 = (idx & 3) << 3;
        size_t base = (size_t)(b * NWIN + n) * (3 * CH) + h * HD + d8;
        *(uint4*)&sq[n * QR + d8] = *(const uint4*)(qkv + base);
        *(uint4*)&sk[n * QR + d8] = *(const uint4*)(qkv + base + CH);
        *(uint4*)&sv[n * QR + d8] = *(const uint4*)(qkv + base + 2 * CH);
    }
    __syncthreads();

    for (int idx = tid; idx < 625; idx += 256) {
        int np = idx / 25, mp = idx - np * 25;
        int n0 = np * 2, m0 = mp * 2;
        int n1 = n0 + 1, m1 = m0 + 1;
        float a00 = 0.f, a01 = 0.f, a10 = 0.f, a11 = 0.f;
        #pragma unroll
        for (int t = 0; t < 4; ++t) {
            union { uint4 u; __half2 hx[4]; } q0, q1, k0, k1;
            q0.u = *(const uint4*)&sq[n0 * QR + t * 8];
            q1.u = *(const uint4*)&sq[n1 * QR + t * 8];
            k0.u = *(const uint4*)&sk[m0 * QR + t * 8];
            k1.u = *(const uint4*)&sk[m1 * QR + t * 8];
            #pragma unroll
            for (int j = 0; j < 4; ++j) {
                float2 fq0 = __half22float2(q0.hx[j]);
                float2 fq1 = __half22float2(q1.hx[j]);
                float2 fk0 = __half22float2(k0.hx[j]);
                float2 fk1 = __half22float2(k1.hx[j]);
                a00 += fq0.x * fk0.x + fq0.y * fk0.y;
                a01 += fq0.x * fk1.x + fq0.y * fk1.y;
                a10 += fq1.x * fk0.x + fq1.y * fk0.y;
                a11 += fq1.x * fk1.x + fq1.y * fk1.y;
            }
        }
        bool nv = (n1 < NWIN), mv = (m1 < NWIN);
        ss[n0 * 52 + m0] = a00 * SCALE + fb[n0 * NWIN + m0];
        if (mv) ss[n0 * 52 + m1] = a01 * SCALE + fb[n0 * NWIN + m1];
        if (nv) {
            ss[n1 * 52 + m0] = a10 * SCALE + fb[n1 * NWIN + m0];
            if (mv) ss[n1 * 52 + m1] = a11 * SCALE + fb[n1 * NWIN + m1];
        }
    }
    __syncthreads();

    int warp = tid >> 5, lane = tid & 31;
    for (int r = warp; r < NWIN; r += 8) {
        float v1 = ss[r * 52 + lane];
        float v2 = (lane + 32 < NWIN) ? ss[r * 52 + lane + 32] : -1e30f;
        float mx = fmaxf(v1, v2);
        #pragma unroll
        for (int off = 16; off; off >>= 1)
            mx = fmaxf(mx, __shfl_xor_sync(0xffffffffu, mx, off));
        float e1 = expf(v1 - mx);
        float e2 = (lane + 32 < NWIN) ? expf(v2 - mx) : 0.0f;
        float sum = e1 + e2;
        #pragma unroll
        for (int off = 16; off; off >>= 1)
            sum += __shfl_xor_sync(0xffffffffu, sum, off);
        float inv = 1.0f / sum;
        ss[r * 52 + lane] = e1 * inv;
        if (lane + 32 < NWIN) ss[r * 52 + lane + 32] = e2 * inv;
    }
    __syncthreads();

    for (int idx = tid; idx < 400; idx += 256) {
        int np = idx >> 4, dp = idx & 15;
        int n0 = np * 2, n1 = n0 + 1, d = dp * 2;
        const float* p0 = &ss[n0 * 52];
        const float* p1 = &ss[n1 * 52];
        float ax0 = 0.f, ay0 = 0.f, ax1 = 0.f, ay1 = 0.f;
        #pragma unroll 7
        for (int m = 0; m < NWIN; ++m) {
            float2 vf = __half22float2(*(const __half2*)&sv[m * QR + d]);
            float b0 = p0[m], b1 = p1[m];
            ax0 += b0 * vf.x; ay0 += b0 * vf.y;
            ax1 += b1 * vf.x; ay1 += b1 * vf.y;
        }
        size_t ob = (size_t)(b * NWIN + n0) * CH + h * HD + d;
        *(__half2*)(oh + ob) = __floats2half2_rn(ax0, ay0);
        if (n1 < NWIN)
            *(__half2*)(oh + ob + CH) = __floats2half2_rn(ax1, ay1);
    }
}

// ---------------- fused: reverse+roll+residual -> out, then LN2 -> yh ----------------
__global__ __launch_bounds__(128)
void fuse2_kernel(const float* __restrict__ x, const float* __restrict__ proj,
                  const float* __restrict__ gamma, const float* __restrict__ beta,
                  float* __restrict__ out, __half* __restrict__ yh)
{
    int tok = blockIdx.x;
    int b = tok / (HIMG * WIMG);
    int rem = tok - b * (HIMG * WIMG);
    int hp0 = rem / WIMG, wp0 = rem - hp0 * WIMG;
    int hp = hp0 - SSH; if (hp < 0) hp += HIMG;
    int wp = wp0 - SSH; if (wp < 0) wp += WIMG;
    int wh = hp / WS, i = hp - wh * WS;
    int ww = wp / WS, j = wp - ww * WS;
    int src = (b * NW_IMG + wh * 8 + ww) * NWIN + i * WS + j;

    int tid = threadIdx.x;
    int c = tid * 4;
    float4 a = *(const float4*)(x + (size_t)tok * CH + c);
    float4 p = *(const float4*)(proj + (size_t)src * CH + c);
    a.x += p.x; a.y += p.y; a.z += p.z; a.w += p.w;
    *(float4*)(out + (size_t)tok * CH + c) = a;

    float s  = a.x + a.y + a.z + a.w;
    float sq = a.x*a.x + a.y*a.y + a.z*a.z + a.w*a.w;
    #pragma unroll
    for (int off = 16; off; off >>= 1) {
        s  += __shfl_xor_sync(0xffffffffu, s, off);
        sq += __shfl_xor_sync(0xffffffffu, sq, off);
    }
    __shared__ float sh[8];
    int warp = tid >> 5, lane = tid & 31;
    if (lane == 0) { sh[warp] = s; sh[warp + 4] = sq; }
    __syncthreads();
    if (tid == 0) {
        float ts = sh[0] + sh[1] + sh[2] + sh[3];
        float tq = sh[4] + sh[5] + sh[6] + sh[7];
        float mean = ts * (1.0f / CH);
        float var = tq * (1.0f / CH) - mean * mean;
        sh[0] = mean; sh[1] = rsqrtf(var + 1e-5f);
    }
    __syncthreads();
    float mean = sh[0], inv = sh[1];
    float4 g4 = *(const float4*)(gamma + c);
    float4 b4 = *(const float4*)(beta + c);
    __half hh[4];
    hh[0] = __float2half_rn((a.x - mean) * inv * g4.x + b4.x);
    hh[1] = __float2half_rn((a.y - mean) * inv * g4.y + b4.y);
    hh[2] = __float2half_rn((a.z - mean) * inv * g4.z + b4.z);
    hh[3] = __float2half_rn((a.w - mean) * inv * g4.w + b4.w);
    *(uint2*)(yh + (size_t)tok * CH + c) = *(uint2*)hh;
}

// ---------------- launcher ----------------
extern "C" void kernel_launch(void* const* d_in, const int* in_sizes, int n_in,
                              void* d_out, int out_size)
{
    const float* x        = (const float*)d_in[0];
    const float* norm1_g  = (const float*)d_in[1];
    const float* norm1_b  = (const float*)d_in[2];
    const float* qkv_w    = (const float*)d_in[3];
    const float* qkv_b    = (const float*)d_in[4];
    const float* rel_tab  = (const float*)d_in[5];
    const float* proj_w   = (const float*)d_in[6];
    const float* proj_b   = (const float*)d_in[7];
    const float* norm2_g  = (const float*)d_in[8];
    const float* norm2_b  = (const float*)d_in[9];
    const float* fc1_w    = (const float*)d_in[10];
    const float* fc1_b    = (const float*)d_in[11];
    const float* fc2_w    = (const float*)d_in[12];
    const float* fc2_b    = (const float*)d_in[13];
    const int*   rel_idx  = (const int*)d_in[14];
    const float* attn_msk = (const float*)d_in[15];
    float* out = (float*)d_out;

    unsigned char *R1, *R2;
    cudaGetSymbolAddress((void**)&R1, g_R1);
    cudaGetSymbolAddress((void**)&R2, g_R2);
    __half *qkvT, *projT, *fc1T, *fc2T;
    cudaGetSymbolAddress((void**)&qkvT, g_qkvT);
    cudaGetSymbolAddress((void**)&projT, g_projT);
    cudaGetSymbolAddress((void**)&fc1T, g_fc1T);
    cudaGetSymbolAddress((void**)&fc2T, g_fc2T);

    __half* qkv = (__half*)R1;
    float* proj = (float*)(R1 + (size_t)MTOK * 3 * CH * 2);
    float* fusedb = (float*)(R1 + (size_t)600 * 1024 * 1024);
    __half* hid = (__half*)R1;
    __half* act = (__half*)R2;

    cudaFuncSetAttribute(tgemm<0>, cudaFuncAttributeMaxDynamicSharedMemorySize, TGEMM_SMEM);
    cudaFuncSetAttribute(tgemm<1>, cudaFuncAttributeMaxDynamicSharedMemorySize, TGEMM_SMEM);
    cudaFuncSetAttribute(tgemm<2>, cudaFuncAttributeMaxDynamicSharedMemorySize, TGEMM_SMEM);
    cudaFuncSetAttribute(tgemm<3>, cudaFuncAttributeMaxDynamicSharedMemorySize, TGEMM_SMEM);

    // 0) weight transpose + fused bias table
    wsplit_kernel<<<dim3(3 * CH / 32, CH / 32), 256>>>(qkv_w,  qkvT, CH, 3 * CH);
    wsplit_kernel<<<dim3(CH / 32,     CH / 32), 256>>>(proj_w, projT, CH, CH);
    wsplit_kernel<<<dim3(HID / 32,    CH / 32), 256>>>(fc1_w,  fc1T, CH, HID);
    wsplit_kernel<<<dim3(CH / 32,    HID / 32), 256>>>(fc2_w,  fc2T, HID, CH);
    fusedbias_kernel<<<NW_IMG * NHEAD, 256>>>(rel_tab, rel_idx, attn_msk, fusedb);

    // 1) LN1 + shift + window partition
    ln_kernel<<<MTOK, 128>>>(x, norm1_g, norm1_b, act, 1);

    // 2) QKV GEMM -> fp16
    tgemm<3><<<dim3(3 * CH / 128, MTOK / 128), 256, TGEMM_SMEM>>>(
        act, qkvT, qkv_b, nullptr, qkv, MTOK, 3 * CH, CH);

    // 3) attention
    attn_kernel<<<BN * NHEAD, 256>>>(qkv, fusedb, act);

    // 4) proj GEMM -> fp32
    tgemm<0><<<dim3(CH / 128, MTOK / 128), 256, TGEMM_SMEM>>>(
        act, projT, proj_b, proj, nullptr, MTOK, CH, CH);

    // 5+6) reverse + residual -> d_out, fused LN2
    fuse2_kernel<<<MTOK, 128>>>(x, proj, norm2_g, norm2_b, out, act);

    // 7) FC1 + GELU -> fp16 hid
    tgemm<1><<<dim3(HID / 128, MTOK / 128), 256, TGEMM_SMEM>>>(
        act, fc1T, fc1_b, nullptr, hid, MTOK, HID, CH);

    // 8) FC2 + residual into d_out
    tgemm<2><<<dim3(CH / 128, MTOK / 128), 256, TGEMM_SMEM>>>(
        hid, fc2T, fc2_b, out, nullptr, MTOK, CH, HID);

    (void)in_sizes; (void)n_in; (void)out_size;
}

// round 12
// speedup vs baseline: 1.4254x; 1.4109x over previous
#include <cuda_runtime.h>
#include <cuda_fp16.h>
#include <math.h>
#include <stdint.h>

// ---------------- problem constants ----------------
#define BATCH   32
#define HIMG    56
#define WIMG    56
#define CH      512
#define NHEAD   16
#define WS      7
#define SSH     3
#define HD      32
#define NWIN    49
#define NW_IMG  64
#define BN      (BATCH*NW_IMG)      // 2048 windows
#define MTOK    (BN*NWIN)           // 100352 tokens
#define HID     2048
#define SCALE   0.17677669529663687f
#define NN      (NWIN*NWIN)         // 2401

// ---------------- scratch ----------------
__device__ __align__(128) unsigned char g_R1[(size_t)MTOK * HID * 4];
__device__ __align__(128) unsigned char g_R2[(size_t)MTOK * CH * 2];

__device__ __align__(128) __half g_qkvT[3 * CH * CH];
__device__ __align__(128) __half g_projT[CH * CH];
__device__ __align__(128) __half g_fc1T[HID * CH];
__device__ __align__(128) __half g_fc2T[CH * HID];

// ---------------- helpers ----------------
__device__ __forceinline__ uint32_t smem_u32(const void* p) {
    uint32_t a;
    asm("{ .reg .u64 t; cvta.to.shared.u64 t, %1; cvt.u32.u64 %0, t; }" : "=r"(a) : "l"(p));
    return a;
}
#define CP16(dst, src) \
    asm volatile("cp.async.cg.shared.global [%0], [%1], 16;" :: "r"(dst), "l"(src))
#define CPCOMMIT() asm volatile("cp.async.commit_group;" ::: "memory")
#define CPWAIT1()  asm volatile("cp.async.wait_group 1;" ::: "memory")
#define CPWAIT0()  asm volatile("cp.async.wait_group 0;" ::: "memory")

#define LDSM4(r, a) \
    asm volatile("ldmatrix.sync.aligned.m8n8.x4.shared.b16 {%0,%1,%2,%3}, [%4];" \
        : "=r"((r)[0]), "=r"((r)[1]), "=r"((r)[2]), "=r"((r)[3]) : "r"(a))

__device__ __forceinline__ void mma_f16(float* c, const uint32_t* a, const uint32_t* b) {
    asm volatile("mma.sync.aligned.m16n8k16.row.col.f32.f16.f16.f32 "
        "{%0,%1,%2,%3}, {%4,%5,%6,%7}, {%8,%9}, {%0,%1,%2,%3};"
        : "+f"(c[0]), "+f"(c[1]), "+f"(c[2]), "+f"(c[3])
        : "r"(a[0]), "r"(a[1]), "r"(a[2]), "r"(a[3]), "r"(b[0]), "r"(b[1]));
}

// ---------------- weight transpose: W[K,N] -> Wt[N,K] fp16 ----------------
__global__ __launch_bounds__(256)
void wsplit_kernel(const float* __restrict__ W, __half* __restrict__ oh, int K, int N)
{
    __shared__ float t[32][33];
    int n0 = blockIdx.x * 32, k0 = blockIdx.y * 32;
    int tx = threadIdx.x & 31, ty = threadIdx.x >> 5;
    #pragma unroll
    for (int i = ty; i < 32; i += 8)
        t[i][tx] = W[(size_t)(k0 + i) * N + n0 + tx];
    __syncthreads();
    #pragma unroll
    for (int i = ty; i < 32; i += 8)
        oh[(size_t)(n0 + i) * K + k0 + tx] = __float2half_rn(t[tx][i]);
}

// ---------------- fused rel-pos bias + window mask table ----------------
__global__ __launch_bounds__(256)
void fusedbias_kernel(const float* __restrict__ table, const int* __restrict__ relidx,
                      const float* __restrict__ mask, float* __restrict__ fusedb)
{
    int wi = blockIdx.x >> 4, h = blockIdx.x & 15;
    float* dst = fusedb + (size_t)blockIdx.x * NN;
    const float* mrow = mask + (size_t)wi * NN;
    for (int i = threadIdx.x; i < NN; i += 256)
        dst[i] = table[relidx[i] * NHEAD + h] + mrow[i];
}

// ---------------- LayerNorm -> fp16 (mode1: shift+partition) ----------------
__global__ __launch_bounds__(128)
void ln_kernel(const float* __restrict__ x, const float* __restrict__ gamma,
               const float* __restrict__ beta, __half* __restrict__ oh, int mode)
{
    int tok = blockIdx.x;
    int src;
    if (mode == 1) {
        int w = tok / NWIN, n = tok - w * NWIN;
        int b = w >> 6, wi = w & 63;
        int wh = wi >> 3, ww = wi & 7;
        int i = n / WS, j = n - i * WS;
        int hp = wh * WS + i, wp = ww * WS + j;
        int hs = hp + SSH; if (hs >= HIMG) hs -= HIMG;
        int ws_ = wp + SSH; if (ws_ >= WIMG) ws_ -= WIMG;
        src = b * (HIMG * WIMG) + hs * WIMG + ws_;
    } else {
        src = tok;
    }
    int tid = threadIdx.x;
    int c = tid * 4;
    float4 v = *(const float4*)(x + (size_t)src * CH + c);
    float s  = v.x + v.y + v.z + v.w;
    float sq = v.x*v.x + v.y*v.y + v.z*v.z + v.w*v.w;
    #pragma unroll
    for (int off = 16; off; off >>= 1) {
        s  += __shfl_xor_sync(0xffffffffu, s, off);
        sq += __shfl_xor_sync(0xffffffffu, sq, off);
    }
    __shared__ float sh[8];
    int warp = tid >> 5, lane = tid & 31;
    if (lane == 0) { sh[warp] = s; sh[warp + 4] = sq; }
    __syncthreads();
    if (tid == 0) {
        float ts = sh[0] + sh[1] + sh[2] + sh[3];
        float tq = sh[4] + sh[5] + sh[6] + sh[7];
        float mean = ts * (1.0f / CH);
        float var = tq * (1.0f / CH) - mean * mean;
        sh[0] = mean; sh[1] = rsqrtf(var + 1e-5f);
    }
    __syncthreads();
    float mean = sh[0], inv = sh[1];
    float4 g4 = *(const float4*)(gamma + c);
    float4 b4 = *(const float4*)(beta + c);
    __half hh[4];
    hh[0] = __float2half_rn((v.x - mean) * inv * g4.x + b4.x);
    hh[1] = __float2half_rn((v.y - mean) * inv * g4.y + b4.y);
    hh[2] = __float2half_rn((v.z - mean) * inv * g4.z + b4.z);
    hh[3] = __float2half_rn((v.w - mean) * inv * g4.w + b4.w);
    *(uint2*)(oh + (size_t)tok * CH + c) = *(uint2*)hh;
}

// ---------------- fp16 GEMM via mma.sync (R9, f32 accumulate) ----------------
#define OFF_B   16384
#define STG_SZ  32768
#define TGEMM_SMEM (3 * STG_SZ)

template <int EPI>
__global__ void __launch_bounds__(256, 2)
tgemm(const __half* __restrict__ Ah, const __half* __restrict__ Bh,
      const float* __restrict__ bias, float* __restrict__ C,
      __half* __restrict__ Ch, int M, int N, int K)
{
    extern __shared__ __align__(128) char smem[];
    uint32_t sb = smem_u32(smem);
    int tid = threadIdx.x, wid = tid >> 5, lane = tid & 31;
    int m0 = blockIdx.y << 7, n0 = blockIdx.x << 7;
    int wm = wid & 3, wn = wid >> 2;

    int ar = tid >> 1, ac = (tid & 1) * 4;
    const char* gA = (const char*)(Ah + (size_t)(m0 + ar) * K) + ac * 16;
    const char* gB = (const char*)(Bh + (size_t)(n0 + ar) * K) + ac * 16;
    uint32_t sw[4];
    #pragma unroll
    for (int j = 0; j < 4; ++j)
        sw[j] = (uint32_t)(ar * 128 + (((ac + j) ^ (ar & 7)) << 4));

    int arow = wm * 32 + (lane & 15);
    uint32_t aterm = (uint32_t)(arow * 128);
    int axor = arow & 7;
    int ac16 = lane >> 4;
    int brow = wn * 64 + ((lane >> 4) & 1) * 8 + (lane & 7);
    uint32_t bterm = (uint32_t)(brow * 128);
    int bxor = brow & 7;
    int bc16 = (lane >> 3) & 1;

    float acc[2][8][4];
    #pragma unroll
    for (int i = 0; i < 2; ++i)
        #pragma unroll
        for (int j = 0; j < 8; ++j)
            #pragma unroll
            for (int q = 0; q < 4; ++q) acc[i][j][q] = 0.0f;

    const int nch = K >> 6;

    #pragma unroll
    for (int pc = 0; pc < 2; ++pc) {
        uint32_t s = sb + pc * STG_SZ;
        size_t go = (size_t)pc * 128;
        #pragma unroll
        for (int j = 0; j < 4; ++j) {
            CP16(s + sw[j],         gA + go + j * 16);
            CP16(s + OFF_B + sw[j], gB + go + j * 16);
        }
        CPCOMMIT();
    }

    int buf = 0;
    for (int c = 0; c < nch; ++c) {
        if (c + 1 < nch) { CPWAIT1(); } else { CPWAIT0(); }
        __syncthreads();
        if (c + 2 < nch) {
            int b2 = buf + 2; if (b2 >= 3) b2 -= 3;
            uint32_t s = sb + b2 * STG_SZ;
            size_t go = (size_t)(c + 2) * 128;
            #pragma unroll
            for (int j = 0; j < 4; ++j) {
                CP16(s + sw[j],         gA + go + j * 16);
                CP16(s + OFF_B + sw[j], gB + go + j * 16);
            }
            CPCOMMIT();
        } else {
            CPCOMMIT();
        }

        uint32_t sS = sb + buf * STG_SZ;
        #pragma unroll
        for (int k16 = 0; k16 < 4; ++k16) {
            uint32_t ah[2][4];
            uint32_t aoff = aterm + ((uint32_t)((2 * k16 + ac16) ^ axor) << 4);
            LDSM4(ah[0], sS + aoff);
            LDSM4(ah[1], sS + aoff + 2048);
            uint32_t boff = bterm + ((uint32_t)((2 * k16 + bc16) ^ bxor) << 4);
            #pragma unroll
            for (int ng = 0; ng < 4; ++ng) {
                uint32_t bh[4];
                LDSM4(bh, sS + OFF_B + boff + ng * 2048);
                #pragma unroll
                for (int mt = 0; mt < 2; ++mt) {
                    mma_f16(acc[mt][2 * ng],     ah[mt], &bh[0]);
                    mma_f16(acc[mt][2 * ng + 1], ah[mt], &bh[2]);
                }
            }
        }
        if (++buf == 3) buf = 0;
    }

    int r0 = m0 + wm * 32 + (lane >> 2);
    int cb = n0 + wn * 64 + (lane & 3) * 2;
    #pragma unroll
    for (int mt = 0; mt < 2; ++mt) {
        #pragma unroll
        for (int n8 = 0; n8 < 8; ++n8) {
            int col = cb + n8 * 8;
            float2 bv = *(const float2*)(bias + col);
            #pragma unroll
            for (int rt = 0; rt < 2; ++rt) {
                int row = r0 + mt * 16 + rt * 8;
                float vx = acc[mt][n8][rt * 2]     + bv.x;
                float vy = acc[mt][n8][rt * 2 + 1] + bv.y;
                if (EPI == 0) {
                    float2 r = {vx, vy};
                    *(float2*)(C + (size_t)row * N + col) = r;
                } else if (EPI == 1) {
                    float gx = 0.5f * vx * (1.0f + erff(vx * 0.70710678118654752f));
                    float gy = 0.5f * vy * (1.0f + erff(vy * 0.70710678118654752f));
                    __half hh[2];
                    hh[0] = __float2half_rn(gx);
                    hh[1] = __float2half_rn(gy);
                    *(uint32_t*)(Ch + (size_t)row * N + col) = *(uint32_t*)hh;
                } else if (EPI == 2) {
                    float* cp = C + (size_t)row * N + col;
                    float2 old = *(const float2*)cp;
                    float2 r = {vx + old.x, vy + old.y};
                    *(float2*)cp = r;
                } else {
                    __half hh[2];
                    hh[0] = __float2half_rn(vx);
                    hh[1] = __float2half_rn(vy);
                    *(uint32_t*)(Ch + (size_t)row * N + col) = *(uint32_t*)hh;
                }
            }
        }
    }
}

// ---------------- HMMA windowed attention ----------------
// one block per (window, head); Q,K padded to 64 rows; S = 64x64; PV = 64x32.
#define SQR 40   // q/k row stride (halves) = 80B, ldmatrix conflict-free
#define SPR 72   // p / v^T row stride (halves) = 144B, conflict-free
#define SSP 68   // score row stride (floats)
__global__ __launch_bounds__(256)
void attn_kernel(const __half* __restrict__ qkv, const float* __restrict__ fusedb,
                 __half* __restrict__ oh)
{
    __shared__ __half sq[64 * SQR], sk[64 * SQR], svt[32 * SPR], sp[64 * SPR];
    __shared__ float ss[64 * SSP];

    int bh = blockIdx.x;
    int b = bh >> 4, h = bh & 15;
    int tid = threadIdx.x, wid = tid >> 5, lane = tid & 31;
    const float* fb = fusedb + (size_t)(((b & 63) << 4) + h) * NN;

    // zero v^T padding cols m=49..63 (NaN safety for PV mma)
    for (int idx = tid; idx < 32 * 15; idx += 256) {
        int d = idx / 15, m = 49 + idx % 15;
        svt[d * SPR + m] = __float2half_rn(0.0f);
    }
    // load q, k rows (49 x 32 halves = 4 x uint4 per row)
    for (int idx = tid; idx < NWIN * 4; idx += 256) {
        int n = idx >> 2, c8 = (idx & 3) << 3;
        size_t base = (size_t)(b * NWIN + n) * (3 * CH) + h * HD + c8;
        *(uint4*)&sq[n * SQR + c8] = *(const uint4*)(qkv + base);
        *(uint4*)&sk[n * SQR + c8] = *(const uint4*)(qkv + base + CH);
    }
    // load v transposed: svt[d][m]
    for (int idx = tid; idx < NWIN * 16; idx += 256) {
        int m = idx >> 4, d = (idx & 15) * 2;
        __half2 v = *(const __half2*)(qkv + (size_t)(b * NWIN + m) * (3 * CH) + 2 * CH + h * HD + d);
        svt[d * SPR + m]       = __low2half(v);
        svt[(d + 1) * SPR + m] = __high2half(v);
    }
    __syncthreads();

    int wm = wid & 3, wn = wid >> 2;

    // ---- S = Q @ K^T (64x64x32) ----
    {
        uint32_t aQ = smem_u32(sq) + (uint32_t)((wm * 16 + (lane & 15)) * (SQR * 2)) + (uint32_t)((lane >> 4) * 16);
        uint32_t bK = smem_u32(sk) + (uint32_t)((wn * 32 + ((lane >> 4) & 1) * 8 + (lane & 7)) * (SQR * 2))
                    + (uint32_t)(((lane >> 3) & 1) * 16);
        float acc[4][4];
        #pragma unroll
        for (int f = 0; f < 4; ++f)
            #pragma unroll
            for (int q = 0; q < 4; ++q) acc[f][q] = 0.0f;

        #pragma unroll
        for (int ks = 0; ks < 2; ++ks) {
            uint32_t af[4];
            LDSM4(af, aQ + ks * 32);
            #pragma unroll
            for (int half = 0; half < 2; ++half) {
                uint32_t bf[4];
                LDSM4(bf, bK + half * 16 * (SQR * 2) + ks * 32);
                mma_f16(acc[half * 2 + 0], af, &bf[0]);
                mma_f16(acc[half * 2 + 1], af, &bf[2]);
            }
        }

        // bias + mask + padding, store fp32 scores
        int r1 = wm * 16 + (lane >> 2), r2 = r1 + 8;
        #pragma unroll
        for (int f = 0; f < 4; ++f) {
            int c = wn * 32 + f * 8 + (lane & 3) * 2;
            ss[r1 * SSP + c]     = (r1 < NWIN && c < NWIN)     ? acc[f][0] * SCALE + fb[r1 * NWIN + c]     : -1e30f;
            ss[r1 * SSP + c + 1] = (r1 < NWIN && c + 1 < NWIN) ? acc[f][1] * SCALE + fb[r1 * NWIN + c + 1] : -1e30f;
            ss[r2 * SSP + c]     = (r2 < NWIN && c < NWIN)     ? acc[f][2] * SCALE + fb[r2 * NWIN + c]     : -1e30f;
            ss[r2 * SSP + c + 1] = (r2 < NWIN && c + 1 < NWIN) ? acc[f][3] * SCALE + fb[r2 * NWIN + c + 1] : -1e30f;
        }
    }
    __syncthreads();

    // ---- softmax rows 0..48 over 64 cols (padding = -1e30 -> 0) ----
    for (int r = wid; r < NWIN; r += 8) {
        float v1 = ss[r * SSP + lane];
        float v2 = ss[r * SSP + lane + 32];
        float mx = fmaxf(v1, v2);
        #pragma unroll
        for (int off = 16; off; off >>= 1)
            mx = fmaxf(mx, __shfl_xor_sync(0xffffffffu, mx, off));
        float e1 = expf(v1 - mx);
        float e2 = expf(v2 - mx);
        float sum = e1 + e2;
        #pragma unroll
        for (int off = 16; off; off >>= 1)
            sum += __shfl_xor_sync(0xffffffffu, sum, off);
        float inv = 1.0f / sum;
        ss[r * SSP + lane]      = e1 * inv;
        ss[r * SSP + lane + 32] = e2 * inv;
    }
    __syncthreads();

    // ---- P -> fp16 (rows >= 49 zeroed) ----
    for (int idx = tid; idx < 64 * 32; idx += 256) {
        int r = idx >> 5, c2 = (idx & 31) * 2;
        __half2 hv;
        if (r < NWIN) {
            float2 pv = *(const float2*)&ss[r * SSP + c2];
            hv = __floats2half2_rn(pv.x, pv.y);
        } else {
            hv = __floats2half2_rn(0.0f, 0.0f);
        }
        *(__half2*)&sp[r * SPR + c2] = hv;
    }
    __syncthreads();

    // ---- O = P @ V (64x32x64) ----
    {
        uint32_t aP = smem_u32(sp) + (uint32_t)((wm * 16 + (lane & 15)) * (SPR * 2)) + (uint32_t)((lane >> 4) * 16);
        uint32_t bV = smem_u32(svt) + (uint32_t)((wn * 16 + ((lane >> 4) & 1) * 8 + (lane & 7)) * (SPR * 2))
                    + (uint32_t)(((lane >> 3) & 1) * 16);
        float acc2[2][4];
        #pragma unroll
        for (int f = 0; f < 2; ++f)
            #pragma unroll
            for (int q = 0; q < 4; ++q) acc2[f][q] = 0.0f;

        #pragma unroll
        for (int ks = 0; ks < 4; ++ks) {
            uint32_t af[4], bf[4];
            LDSM4(af, aP + ks * 32);
            LDSM4(bf, bV + ks * 32);
            mma_f16(acc2[0], af, &bf[0]);
            mma_f16(acc2[1], af, &bf[2]);
        }

        int r1 = wm * 16 + (lane >> 2), r2 = r1 + 8;
        #pragma unroll
        for (int f = 0; f < 2; ++f) {
            int c = wn * 16 + f * 8 + (lane & 3) * 2;
            if (r1 < NWIN)
                *(__half2*)(oh + (size_t)(b * NWIN + r1) * CH + h * HD + c) =
                    __floats2half2_rn(acc2[f][0], acc2[f][1]);
            if (r2 < NWIN)
                *(__half2*)(oh + (size_t)(b * NWIN + r2) * CH + h * HD + c) =
                    __floats2half2_rn(acc2[f][2], acc2[f][3]);
        }
    }
}

// ---------------- fused: reverse+roll+residual -> out, then LN2 -> yh ----------------
__global__ __launch_bounds__(128)
void fuse2_kernel(const float* __restrict__ x, const float* __restrict__ proj,
                  const float* __restrict__ gamma, const float* __restrict__ beta,
                  float* __restrict__ out, __half* __restrict__ yh)
{
    int tok = blockIdx.x;
    int b = tok / (HIMG * WIMG);
    int rem = tok - b * (HIMG * WIMG);
    int hp0 = rem / WIMG, wp0 = rem - hp0 * WIMG;
    int hp = hp0 - SSH; if (hp < 0) hp += HIMG;
    int wp = wp0 - SSH; if (wp < 0) wp += WIMG;
    int wh = hp / WS, i = hp - wh * WS;
    int ww = wp / WS, j = wp - ww * WS;
    int src = (b * NW_IMG + wh * 8 + ww) * NWIN + i * WS + j;

    int tid = threadIdx.x;
    int c = tid * 4;
    float4 a = *(const float4*)(x + (size_t)tok * CH + c);
    float4 p = *(const float4*)(proj + (size_t)src * CH + c);
    a.x += p.x; a.y += p.y; a.z += p.z; a.w += p.w;
    *(float4*)(out + (size_t)tok * CH + c) = a;

    float s  = a.x + a.y + a.z + a.w;
    float sq = a.x*a.x + a.y*a.y + a.z*a.z + a.w*a.w;
    #pragma unroll
    for (int off = 16; off; off >>= 1) {
        s  += __shfl_xor_sync(0xffffffffu, s, off);
        sq += __shfl_xor_sync(0xffffffffu, sq, off);
    }
    __shared__ float sh[8];
    int warp = tid >> 5, lane = tid & 31;
    if (lane == 0) { sh[warp] = s; sh[warp + 4] = sq; }
    __syncthreads();
    if (tid == 0) {
        float ts = sh[0] + sh[1] + sh[2] + sh[3];
        float tq = sh[4] + sh[5] + sh[6] + sh[7];
        float mean = ts * (1.0f / CH);
        float var = tq * (1.0f / CH) - mean * mean;
        sh[0] = mean; sh[1] = rsqrtf(var + 1e-5f);
    }
    __syncthreads();
    float mean = sh[0], inv = sh[1];
    float4 g4 = *(const float4*)(gamma + c);
    float4 b4 = *(const float4*)(beta + c);
    __half hh[4];
    hh[0] = __float2half_rn((a.x - mean) * inv * g4.x + b4.x);
    hh[1] = __float2half_rn((a.y - mean) * inv * g4.y + b4.y);
    hh[2] = __float2half_rn((a.z - mean) * inv * g4.z + b4.z);
    hh[3] = __float2half_rn((a.w - mean) * inv * g4.w + b4.w);
    *(uint2*)(yh + (size_t)tok * CH + c) = *(uint2*)hh;
}

// ---------------- launcher ----------------
extern "C" void kernel_launch(void* const* d_in, const int* in_sizes, int n_in,
                              void* d_out, int out_size)
{
    const float* x        = (const float*)d_in[0];
    const float* norm1_g  = (const float*)d_in[1];
    const float* norm1_b  = (const float*)d_in[2];
    const float* qkv_w    = (const float*)d_in[3];
    const float* qkv_b    = (const float*)d_in[4];
    const float* rel_tab  = (const float*)d_in[5];
    const float* proj_w   = (const float*)d_in[6];
    const float* proj_b   = (const float*)d_in[7];
    const float* norm2_g  = (const float*)d_in[8];
    const float* norm2_b  = (const float*)d_in[9];
    const float* fc1_w    = (const float*)d_in[10];
    const float* fc1_b    = (const float*)d_in[11];
    const float* fc2_w    = (const float*)d_in[12];
    const float* fc2_b    = (const float*)d_in[13];
    const int*   rel_idx  = (const int*)d_in[14];
    const float* attn_msk = (const float*)d_in[15];
    float* out = (float*)d_out;

    unsigned char *R1, *R2;
    cudaGetSymbolAddress((void**)&R1, g_R1);
    cudaGetSymbolAddress((void**)&R2, g_R2);
    __half *qkvT, *projT, *fc1T, *fc2T;
    cudaGetSymbolAddress((void**)&qkvT, g_qkvT);
    cudaGetSymbolAddress((void**)&projT, g_projT);
    cudaGetSymbolAddress((void**)&fc1T, g_fc1T);
    cudaGetSymbolAddress((void**)&fc2T, g_fc2T);

    __half* qkv = (__half*)R1;
    float* proj = (float*)(R1 + (size_t)MTOK * 3 * CH * 2);
    float* fusedb = (float*)(R1 + (size_t)600 * 1024 * 1024);
    __half* hid = (__half*)R1;
    __half* act = (__half*)R2;

    cudaFuncSetAttribute(tgemm<0>, cudaFuncAttributeMaxDynamicSharedMemorySize, TGEMM_SMEM);
    cudaFuncSetAttribute(tgemm<1>, cudaFuncAttributeMaxDynamicSharedMemorySize, TGEMM_SMEM);
    cudaFuncSetAttribute(tgemm<2>, cudaFuncAttributeMaxDynamicSharedMemorySize, TGEMM_SMEM);
    cudaFuncSetAttribute(tgemm<3>, cudaFuncAttributeMaxDynamicSharedMemorySize, TGEMM_SMEM);

    // 0) weight transpose + fused bias table
    wsplit_kernel<<<dim3(3 * CH / 32, CH / 32), 256>>>(qkv_w,  qkvT, CH, 3 * CH);
    wsplit_kernel<<<dim3(CH / 32,     CH / 32), 256>>>(proj_w, projT, CH, CH);
    wsplit_kernel<<<dim3(HID / 32,    CH / 32), 256>>>(fc1_w,  fc1T, CH, HID);
    wsplit_kernel<<<dim3(CH / 32,    HID / 32), 256>>>(fc2_w,  fc2T, HID, CH);
    fusedbias_kernel<<<NW_IMG * NHEAD, 256>>>(rel_tab, rel_idx, attn_msk, fusedb);

    // 1) LN1 + shift + window partition
    ln_kernel<<<MTOK, 128>>>(x, norm1_g, norm1_b, act, 1);

    // 2) QKV GEMM -> fp16
    tgemm<3><<<dim3(3 * CH / 128, MTOK / 128), 256, TGEMM_SMEM>>>(
        act, qkvT, qkv_b, nullptr, qkv, MTOK, 3 * CH, CH);

    // 3) attention (HMMA)
    attn_kernel<<<BN * NHEAD, 256>>>(qkv, fusedb, act);

    // 4) proj GEMM -> fp32
    tgemm<0><<<dim3(CH / 128, MTOK / 128), 256, TGEMM_SMEM>>>(
        act, projT, proj_b, proj, nullptr, MTOK, CH, CH);

    // 5+6) reverse + residual -> d_out, fused LN2
    fuse2_kernel<<<MTOK, 128>>>(x, proj, norm2_g, norm2_b, out, act);

    // 7) FC1 + GELU -> fp16 hid
    tgemm<1><<<dim3(HID / 128, MTOK / 128), 256, TGEMM_SMEM>>>(
        act, fc1T, fc1_b, nullptr, hid, MTOK, HID, CH);

    // 8) FC2 + residual into d_out
    tgemm<2><<<dim3(CH / 128, MTOK / 128), 256, TGEMM_SMEM>>>(
        hid, fc2T, fc2_b, out, nullptr, MTOK, CH, HID);

    (void)in_sizes; (void)n_in; (void)out_size;
}

// round 13
// speedup vs baseline: 1.4466x; 1.0149x over previous
#include <cuda_runtime.h>
#include <cuda_fp16.h>
#include <math.h>
#include <stdint.h>

// ---------------- problem constants ----------------
#define BATCH   32
#define HIMG    56
#define WIMG    56
#define CH      512
#define NHEAD   16
#define WS      7
#define SSH     3
#define HD      32
#define NWIN    49
#define NW_IMG  64
#define BN      (BATCH*NW_IMG)      // 2048 windows
#define MTOK    (BN*NWIN)           // 100352 tokens
#define HID     2048
#define SCALE   0.17677669529663687f
#define NN      (NWIN*NWIN)         // 2401

// ---------------- scratch ----------------
__device__ __align__(128) unsigned char g_R1[(size_t)MTOK * HID * 4];
__device__ __align__(128) unsigned char g_R2[(size_t)MTOK * CH * 2];

__device__ __align__(128) __half g_qkvT[3 * CH * CH];
__device__ __align__(128) __half g_projT[CH * CH];
__device__ __align__(128) __half g_fc1T[HID * CH];
__device__ __align__(128) __half g_fc2T[CH * HID];

// ---------------- helpers ----------------
__device__ __forceinline__ uint32_t smem_u32(const void* p) {
    uint32_t a;
    asm("{ .reg .u64 t; cvta.to.shared.u64 t, %1; cvt.u32.u64 %0, t; }" : "=r"(a) : "l"(p));
    return a;
}
#define CP16(dst, src) \
    asm volatile("cp.async.cg.shared.global [%0], [%1], 16;" :: "r"(dst), "l"(src))
#define CPCOMMIT() asm volatile("cp.async.commit_group;" ::: "memory")
#define CPWAIT1()  asm volatile("cp.async.wait_group 1;" ::: "memory")
#define CPWAIT0()  asm volatile("cp.async.wait_group 0;" ::: "memory")

#define LDSM4(r, a) \
    asm volatile("ldmatrix.sync.aligned.m8n8.x4.shared.b16 {%0,%1,%2,%3}, [%4];" \
        : "=r"((r)[0]), "=r"((r)[1]), "=r"((r)[2]), "=r"((r)[3]) : "r"(a))

__device__ __forceinline__ void mma_f16(float* c, const uint32_t* a, const uint32_t* b) {
    asm volatile("mma.sync.aligned.m16n8k16.row.col.f32.f16.f16.f32 "
        "{%0,%1,%2,%3}, {%4,%5,%6,%7}, {%8,%9}, {%0,%1,%2,%3};"
        : "+f"(c[0]), "+f"(c[1]), "+f"(c[2]), "+f"(c[3])
        : "r"(a[0]), "r"(a[1]), "r"(a[2]), "r"(a[3]), "r"(b[0]), "r"(b[1]));
}

// ---------------- unified prep kernel: 4 weight transposes + fused bias ----------------
__device__ __forceinline__ void wsplit_tile(const float* __restrict__ W, __half* __restrict__ oh,
                                            int K, int N, int bx, int by, float (*t)[33])
{
    int n0 = bx * 32, k0 = by * 32;
    int tx = threadIdx.x & 31, ty = threadIdx.x >> 5;
    #pragma unroll
    for (int i = ty; i < 32; i += 8)
        t[i][tx] = W[(size_t)(k0 + i) * N + n0 + tx];
    __syncthreads();
    #pragma unroll
    for (int i = ty; i < 32; i += 8)
        oh[(size_t)(n0 + i) * K + k0 + tx] = __float2half_rn(t[tx][i]);
}

__global__ __launch_bounds__(256)
void prep_kernel(const float* __restrict__ qkv_w, const float* __restrict__ proj_w,
                 const float* __restrict__ fc1_w, const float* __restrict__ fc2_w,
                 __half* __restrict__ qkvT, __half* __restrict__ projT,
                 __half* __restrict__ fc1T, __half* __restrict__ fc2T,
                 const float* __restrict__ table, const int* __restrict__ relidx,
                 const float* __restrict__ mask, float* __restrict__ fusedb)
{
    __shared__ float t[32][33];
    int id = blockIdx.x;
    if (id < 768) {                       // qkv: grid 48 x 16
        wsplit_tile(qkv_w, qkvT, CH, 3 * CH, id % 48, id / 48, t);
    } else if (id < 1024) {               // proj: 16 x 16
        int s = id - 768;
        wsplit_tile(proj_w, projT, CH, CH, s % 16, s / 16, t);
    } else if (id < 2048) {               // fc1: 64 x 16
        int s = id - 1024;
        wsplit_tile(fc1_w, fc1T, CH, HID, s % 64, s / 64, t);
    } else if (id < 3072) {               // fc2: 16 x 64
        int s = id - 2048;
        wsplit_tile(fc2_w, fc2T, HID, CH, s % 16, s / 16, t);
    } else {                              // fused bias: 1024 blocks
        int s = id - 3072;
        int wi = s >> 4, h = s & 15;
        float* dst = fusedb + (size_t)s * NN;
        const float* mrow = mask + (size_t)wi * NN;
        for (int i = threadIdx.x; i < NN; i += 256)
            dst[i] = table[relidx[i] * NHEAD + h] + mrow[i];
    }
}

// ---------------- LayerNorm, warp-per-token (mode1: shift+partition) ----------------
__global__ __launch_bounds__(128)
void ln_kernel(const float* __restrict__ x, const float* __restrict__ gamma,
               const float* __restrict__ beta, __half* __restrict__ oh, int mode)
{
    int warp = threadIdx.x >> 5, lane = threadIdx.x & 31;
    int tok = blockIdx.x * 4 + warp;
    int src;
    if (mode == 1) {
        int w = tok / NWIN, n = tok - w * NWIN;
        int b = w >> 6, wi = w & 63;
        int wh = wi >> 3, ww = wi & 7;
        int i = n / WS, j = n - i * WS;
        int hp = wh * WS + i, wp = ww * WS + j;
        int hs = hp + SSH; if (hs >= HIMG) hs -= HIMG;
        int ws_ = wp + SSH; if (ws_ >= WIMG) ws_ -= WIMG;
        src = b * (HIMG * WIMG) + hs * WIMG + ws_;
    } else {
        src = tok;
    }
    const float* xp = x + (size_t)src * CH;
    float4 v[4];
    float s = 0.0f, sq = 0.0f;
    #pragma unroll
    for (int k = 0; k < 4; ++k) {
        v[k] = *(const float4*)(xp + k * 128 + lane * 4);
        s  += v[k].x + v[k].y + v[k].z + v[k].w;
        sq += v[k].x*v[k].x + v[k].y*v[k].y + v[k].z*v[k].z + v[k].w*v[k].w;
    }
    #pragma unroll
    for (int off = 16; off; off >>= 1) {
        s  += __shfl_xor_sync(0xffffffffu, s, off);
        sq += __shfl_xor_sync(0xffffffffu, sq, off);
    }
    float mean = s * (1.0f / CH);
    float inv = rsqrtf(sq * (1.0f / CH) - mean * mean + 1e-5f);
    __half* op = oh + (size_t)tok * CH;
    #pragma unroll
    for (int k = 0; k < 4; ++k) {
        int c = k * 128 + lane * 4;
        float4 g4 = *(const float4*)(gamma + c);
        float4 b4 = *(const float4*)(beta + c);
        __half hh[4];
        hh[0] = __float2half_rn((v[k].x - mean) * inv * g4.x + b4.x);
        hh[1] = __float2half_rn((v[k].y - mean) * inv * g4.y + b4.y);
        hh[2] = __float2half_rn((v[k].z - mean) * inv * g4.z + b4.z);
        hh[3] = __float2half_rn((v[k].w - mean) * inv * g4.w + b4.w);
        *(uint2*)(op + c) = *(uint2*)hh;
    }
}

// ---------------- fp16 GEMM via mma.sync (R9, f32 accumulate) ----------------
#define OFF_B   16384
#define STG_SZ  32768
#define TGEMM_SMEM (3 * STG_SZ)

template <int EPI>
__global__ void __launch_bounds__(256, 2)
tgemm(const __half* __restrict__ Ah, const __half* __restrict__ Bh,
      const float* __restrict__ bias, float* __restrict__ C,
      __half* __restrict__ Ch, int M, int N, int K)
{
    extern __shared__ __align__(128) char smem[];
    uint32_t sb = smem_u32(smem);
    int tid = threadIdx.x, wid = tid >> 5, lane = tid & 31;
    int m0 = blockIdx.y << 7, n0 = blockIdx.x << 7;
    int wm = wid & 3, wn = wid >> 2;

    int ar = tid >> 1, ac = (tid & 1) * 4;
    const char* gA = (const char*)(Ah + (size_t)(m0 + ar) * K) + ac * 16;
    const char* gB = (const char*)(Bh + (size_t)(n0 + ar) * K) + ac * 16;
    uint32_t sw[4];
    #pragma unroll
    for (int j = 0; j < 4; ++j)
        sw[j] = (uint32_t)(ar * 128 + (((ac + j) ^ (ar & 7)) << 4));

    int arow = wm * 32 + (lane & 15);
    uint32_t aterm = (uint32_t)(arow * 128);
    int axor = arow & 7;
    int ac16 = lane >> 4;
    int brow = wn * 64 + ((lane >> 4) & 1) * 8 + (lane & 7);
    uint32_t bterm = (uint32_t)(brow * 128);
    int bxor = brow & 7;
    int bc16 = (lane >> 3) & 1;

    float acc[2][8][4];
    #pragma unroll
    for (int i = 0; i < 2; ++i)
        #pragma unroll
        for (int j = 0; j < 8; ++j)
            #pragma unroll
            for (int q = 0; q < 4; ++q) acc[i][j][q] = 0.0f;

    const int nch = K >> 6;

    #pragma unroll
    for (int pc = 0; pc < 2; ++pc) {
        uint32_t s = sb + pc * STG_SZ;
        size_t go = (size_t)pc * 128;
        #pragma unroll
        for (int j = 0; j < 4; ++j) {
            CP16(s + sw[j],         gA + go + j * 16);
            CP16(s + OFF_B + sw[j], gB + go + j * 16);
        }
        CPCOMMIT();
    }

    int buf = 0;
    for (int c = 0; c < nch; ++c) {
        if (c + 1 < nch) { CPWAIT1(); } else { CPWAIT0(); }
        __syncthreads();
        if (c + 2 < nch) {
            int b2 = buf + 2; if (b2 >= 3) b2 -= 3;
            uint32_t s = sb + b2 * STG_SZ;
            size_t go = (size_t)(c + 2) * 128;
            #pragma unroll
            for (int j = 0; j < 4; ++j) {
                CP16(s + sw[j],         gA + go + j * 16);
                CP16(s + OFF_B + sw[j], gB + go + j * 16);
            }
            CPCOMMIT();
        } else {
            CPCOMMIT();
        }

        uint32_t sS = sb + buf * STG_SZ;
        #pragma unroll
        for (int k16 = 0; k16 < 4; ++k16) {
            uint32_t ah[2][4];
            uint32_t aoff = aterm + ((uint32_t)((2 * k16 + ac16) ^ axor) << 4);
            LDSM4(ah[0], sS + aoff);
            LDSM4(ah[1], sS + aoff + 2048);
            uint32_t boff = bterm + ((uint32_t)((2 * k16 + bc16) ^ bxor) << 4);
            #pragma unroll
            for (int ng = 0; ng < 4; ++ng) {
                uint32_t bh[4];
                LDSM4(bh, sS + OFF_B + boff + ng * 2048);
                #pragma unroll
                for (int mt = 0; mt < 2; ++mt) {
                    mma_f16(acc[mt][2 * ng],     ah[mt], &bh[0]);
                    mma_f16(acc[mt][2 * ng + 1], ah[mt], &bh[2]);
                }
            }
        }
        if (++buf == 3) buf = 0;
    }

    int r0 = m0 + wm * 32 + (lane >> 2);
    int cb = n0 + wn * 64 + (lane & 3) * 2;
    #pragma unroll
    for (int mt = 0; mt < 2; ++mt) {
        #pragma unroll
        for (int n8 = 0; n8 < 8; ++n8) {
            int col = cb + n8 * 8;
            float2 bv = *(const float2*)(bias + col);
            #pragma unroll
            for (int rt = 0; rt < 2; ++rt) {
                int row = r0 + mt * 16 + rt * 8;
                float vx = acc[mt][n8][rt * 2]     + bv.x;
                float vy = acc[mt][n8][rt * 2 + 1] + bv.y;
                if (EPI == 0) {
                    float2 r = {vx, vy};
                    *(float2*)(C + (size_t)row * N + col) = r;
                } else if (EPI == 1) {
                    float gx = 0.5f * vx * (1.0f + erff(vx * 0.70710678118654752f));
                    float gy = 0.5f * vy * (1.0f + erff(vy * 0.70710678118654752f));
                    __half hh[2];
                    hh[0] = __float2half_rn(gx);
                    hh[1] = __float2half_rn(gy);
                    *(uint32_t*)(Ch + (size_t)row * N + col) = *(uint32_t*)hh;
                } else if (EPI == 2) {
                    float* cp = C + (size_t)row * N + col;
                    float2 old = *(const float2*)cp;
                    float2 r = {vx + old.x, vy + old.y};
                    *(float2*)cp = r;
                } else {
                    __half hh[2];
                    hh[0] = __float2half_rn(vx);
                    hh[1] = __float2half_rn(vy);
                    *(uint32_t*)(Ch + (size_t)row * N + col) = *(uint32_t*)hh;
                }
            }
        }
    }
}

// ---------------- HMMA windowed attention (R12) ----------------
#define SQR 40
#define SPR 72
#define SSP 68
__global__ __launch_bounds__(256)
void attn_kernel(const __half* __restrict__ qkv, const float* __restrict__ fusedb,
                 __half* __restrict__ oh)
{
    __shared__ __half sq[64 * SQR], sk[64 * SQR], svt[32 * SPR], sp[64 * SPR];
    __shared__ float ss[64 * SSP];

    int bh = blockIdx.x;
    int b = bh >> 4, h = bh & 15;
    int tid = threadIdx.x, wid = tid >> 5, lane = tid & 31;
    const float* fb = fusedb + (size_t)(((b & 63) << 4) + h) * NN;

    for (int idx = tid; idx < 32 * 15; idx += 256) {
        int d = idx / 15, m = 49 + idx % 15;
        svt[d * SPR + m] = __float2half_rn(0.0f);
    }
    for (int idx = tid; idx < NWIN * 4; idx += 256) {
        int n = idx >> 2, c8 = (idx & 3) << 3;
        size_t base = (size_t)(b * NWIN + n) * (3 * CH) + h * HD + c8;
        *(uint4*)&sq[n * SQR + c8] = *(const uint4*)(qkv + base);
        *(uint4*)&sk[n * SQR + c8] = *(const uint4*)(qkv + base + CH);
    }
    for (int idx = tid; idx < NWIN * 16; idx += 256) {
        int m = idx >> 4, d = (idx & 15) * 2;
        __half2 v = *(const __half2*)(qkv + (size_t)(b * NWIN + m) * (3 * CH) + 2 * CH + h * HD + d);
        svt[d * SPR + m]       = __low2half(v);
        svt[(d + 1) * SPR + m] = __high2half(v);
    }
    __syncthreads();

    int wm = wid & 3, wn = wid >> 2;

    {
        uint32_t aQ = smem_u32(sq) + (uint32_t)((wm * 16 + (lane & 15)) * (SQR * 2)) + (uint32_t)((lane >> 4) * 16);
        uint32_t bK = smem_u32(sk) + (uint32_t)((wn * 32 + ((lane >> 4) & 1) * 8 + (lane & 7)) * (SQR * 2))
                    + (uint32_t)(((lane >> 3) & 1) * 16);
        float acc[4][4];
        #pragma unroll
        for (int f = 0; f < 4; ++f)
            #pragma unroll
            for (int q = 0; q < 4; ++q) acc[f][q] = 0.0f;

        #pragma unroll
        for (int ks = 0; ks < 2; ++ks) {
            uint32_t af[4];
            LDSM4(af, aQ + ks * 32);
            #pragma unroll
            for (int half = 0; half < 2; ++half) {
                uint32_t bf[4];
                LDSM4(bf, bK + half * 16 * (SQR * 2) + ks * 32);
                mma_f16(acc[half * 2 + 0], af, &bf[0]);
                mma_f16(acc[half * 2 + 1], af, &bf[2]);
            }
        }

        int r1 = wm * 16 + (lane >> 2), r2 = r1 + 8;
        #pragma unroll
        for (int f = 0; f < 4; ++f) {
            int c = wn * 32 + f * 8 + (lane & 3) * 2;
            ss[r1 * SSP + c]     = (r1 < NWIN && c < NWIN)     ? acc[f][0] * SCALE + fb[r1 * NWIN + c]     : -1e30f;
            ss[r1 * SSP + c + 1] = (r1 < NWIN && c + 1 < NWIN) ? acc[f][1] * SCALE + fb[r1 * NWIN + c + 1] : -1e30f;
            ss[r2 * SSP + c]     = (r2 < NWIN && c < NWIN)     ? acc[f][2] * SCALE + fb[r2 * NWIN + c]     : -1e30f;
            ss[r2 * SSP + c + 1] = (r2 < NWIN && c + 1 < NWIN) ? acc[f][3] * SCALE + fb[r2 * NWIN + c + 1] : -1e30f;
        }
    }
    __syncthreads();

    for (int r = wid; r < NWIN; r += 8) {
        float v1 = ss[r * SSP + lane];
        float v2 = ss[r * SSP + lane + 32];
        float mx = fmaxf(v1, v2);
        #pragma unroll
        for (int off = 16; off; off >>= 1)
            mx = fmaxf(mx, __shfl_xor_sync(0xffffffffu, mx, off));
        float e1 = expf(v1 - mx);
        float e2 = expf(v2 - mx);
        float sum = e1 + e2;
        #pragma unroll
        for (int off = 16; off; off >>= 1)
            sum += __shfl_xor_sync(0xffffffffu, sum, off);
        float inv = 1.0f / sum;
        ss[r * SSP + lane]      = e1 * inv;
        ss[r * SSP + lane + 32] = e2 * inv;
    }
    __syncthreads();

    for (int idx = tid; idx < 64 * 32; idx += 256) {
        int r = idx >> 5, c2 = (idx & 31) * 2;
        __half2 hv;
        if (r < NWIN) {
            float2 pv = *(const float2*)&ss[r * SSP + c2];
            hv = __floats2half2_rn(pv.x, pv.y);
        } else {
            hv = __floats2half2_rn(0.0f, 0.0f);
        }
        *(__half2*)&sp[r * SPR + c2] = hv;
    }
    __syncthreads();

    {
        uint32_t aP = smem_u32(sp) + (uint32_t)((wm * 16 + (lane & 15)) * (SPR * 2)) + (uint32_t)((lane >> 4) * 16);
        uint32_t bV = smem_u32(svt) + (uint32_t)((wn * 16 + ((lane >> 4) & 1) * 8 + (lane & 7)) * (SPR * 2))
                    + (uint32_t)(((lane >> 3) & 1) * 16);
        float acc2[2][4];
        #pragma unroll
        for (int f = 0; f < 2; ++f)
            #pragma unroll
            for (int q = 0; q < 4; ++q) acc2[f][q] = 0.0f;

        #pragma unroll
        for (int ks = 0; ks < 4; ++ks) {
            uint32_t af[4], bf[4];
            LDSM4(af, aP + ks * 32);
            LDSM4(bf, bV + ks * 32);
            mma_f16(acc2[0], af, &bf[0]);
            mma_f16(acc2[1], af, &bf[2]);
        }

        int r1 = wm * 16 + (lane >> 2), r2 = r1 + 8;
        #pragma unroll
        for (int f = 0; f < 2; ++f) {
            int c = wn * 16 + f * 8 + (lane & 3) * 2;
            if (r1 < NWIN)
                *(__half2*)(oh + (size_t)(b * NWIN + r1) * CH + h * HD + c) =
                    __floats2half2_rn(acc2[f][0], acc2[f][1]);
            if (r2 < NWIN)
                *(__half2*)(oh + (size_t)(b * NWIN + r2) * CH + h * HD + c) =
                    __floats2half2_rn(acc2[f][2], acc2[f][3]);
        }
    }
}

// ---------------- fused: reverse+roll+residual -> out, LN2 -> yh (warp/token) ----------------
__global__ __launch_bounds__(128)
void fuse2_kernel(const float* __restrict__ x, const __half* __restrict__ projh,
                  const float* __restrict__ gamma, const float* __restrict__ beta,
                  float* __restrict__ out, __half* __restrict__ yh)
{
    int warp = threadIdx.x >> 5, lane = threadIdx.x & 31;
    int tok = blockIdx.x * 4 + warp;
    int b = tok / (HIMG * WIMG);
    int rem = tok - b * (HIMG * WIMG);
    int hp0 = rem / WIMG, wp0 = rem - hp0 * WIMG;
    int hp = hp0 - SSH; if (hp < 0) hp += HIMG;
    int wp = wp0 - SSH; if (wp < 0) wp += WIMG;
    int wh = hp / WS, i = hp - wh * WS;
    int ww = wp / WS, j = wp - ww * WS;
    int src = (b * NW_IMG + wh * 8 + ww) * NWIN + i * WS + j;

    const float* xp = x + (size_t)tok * CH;
    const __half* pp = projh + (size_t)src * CH;
    float* op = out + (size_t)tok * CH;

    float4 a[4];
    float s = 0.0f, sq = 0.0f;
    #pragma unroll
    for (int k = 0; k < 4; ++k) {
        int c = k * 128 + lane * 4;
        a[k] = *(const float4*)(xp + c);
        union { uint2 u; __half hx[4]; } ph;
        ph.u = *(const uint2*)(pp + c);
        a[k].x += __half2float(ph.hx[0]);
        a[k].y += __half2float(ph.hx[1]);
        a[k].z += __half2float(ph.hx[2]);
        a[k].w += __half2float(ph.hx[3]);
        *(float4*)(op + c) = a[k];
        s  += a[k].x + a[k].y + a[k].z + a[k].w;
        sq += a[k].x*a[k].x + a[k].y*a[k].y + a[k].z*a[k].z + a[k].w*a[k].w;
    }
    #pragma unroll
    for (int off = 16; off; off >>= 1) {
        s  += __shfl_xor_sync(0xffffffffu, s, off);
        sq += __shfl_xor_sync(0xffffffffu, sq, off);
    }
    float mean = s * (1.0f / CH);
    float inv = rsqrtf(sq * (1.0f / CH) - mean * mean + 1e-5f);
    __half* yp = yh + (size_t)tok * CH;
    #pragma unroll
    for (int k = 0; k < 4; ++k) {
        int c = k * 128 + lane * 4;
        float4 g4 = *(const float4*)(gamma + c);
        float4 b4 = *(const float4*)(beta + c);
        __half hh[4];
        hh[0] = __float2half_rn((a[k].x - mean) * inv * g4.x + b4.x);
        hh[1] = __float2half_rn((a[k].y - mean) * inv * g4.y + b4.y);
        hh[2] = __float2half_rn((a[k].z - mean) * inv * g4.z + b4.z);
        hh[3] = __float2half_rn((a[k].w - mean) * inv * g4.w + b4.w);
        *(uint2*)(yp + c) = *(uint2*)hh;
    }
}

// ---------------- launcher ----------------
extern "C" void kernel_launch(void* const* d_in, const int* in_sizes, int n_in,
                              void* d_out, int out_size)
{
    const float* x        = (const float*)d_in[0];
    const float* norm1_g  = (const float*)d_in[1];
    const float* norm1_b  = (const float*)d_in[2];
    const float* qkv_w    = (const float*)d_in[3];
    const float* qkv_b    = (const float*)d_in[4];
    const float* rel_tab  = (const float*)d_in[5];
    const float* proj_w   = (const float*)d_in[6];
    const float* proj_b   = (const float*)d_in[7];
    const float* norm2_g  = (const float*)d_in[8];
    const float* norm2_b  = (const float*)d_in[9];
    const float* fc1_w    = (const float*)d_in[10];
    const float* fc1_b    = (const float*)d_in[11];
    const float* fc2_w    = (const float*)d_in[12];
    const float* fc2_b    = (const float*)d_in[13];
    const int*   rel_idx  = (const int*)d_in[14];
    const float* attn_msk = (const float*)d_in[15];
    float* out = (float*)d_out;

    unsigned char *R1, *R2;
    cudaGetSymbolAddress((void**)&R1, g_R1);
    cudaGetSymbolAddress((void**)&R2, g_R2);
    __half *qkvT, *projT, *fc1T, *fc2T;
    cudaGetSymbolAddress((void**)&qkvT, g_qkvT);
    cudaGetSymbolAddress((void**)&projT, g_projT);
    cudaGetSymbolAddress((void**)&fc1T, g_fc1T);
    cudaGetSymbolAddress((void**)&fc2T, g_fc2T);

    __half* qkv   = (__half*)R1;                                  // 308MB fp16
    __half* projh = (__half*)(R1 + (size_t)MTOK * 3 * CH * 2);    // 102MB fp16
    float* fusedb = (float*)(R1 + (size_t)600 * 1024 * 1024);     // 9.8MB
    __half* hid   = (__half*)R1;                                  // reuses dead qkv region
    __half* act   = (__half*)R2;                                  // wins -> o -> y

    cudaFuncSetAttribute(tgemm<0>, cudaFuncAttributeMaxDynamicSharedMemorySize, TGEMM_SMEM);
    cudaFuncSetAttribute(tgemm<1>, cudaFuncAttributeMaxDynamicSharedMemorySize, TGEMM_SMEM);
    cudaFuncSetAttribute(tgemm<2>, cudaFuncAttributeMaxDynamicSharedMemorySize, TGEMM_SMEM);
    cudaFuncSetAttribute(tgemm<3>, cudaFuncAttributeMaxDynamicSharedMemorySize, TGEMM_SMEM);

    // 0) unified prep: weight transposes + fused bias (one launch)
    prep_kernel<<<4096, 256>>>(qkv_w, proj_w, fc1_w, fc2_w, qkvT, projT, fc1T, fc2T,
                               rel_tab, rel_idx, attn_msk, fusedb);

    // 1) LN1 + shift + window partition (warp per token)
    ln_kernel<<<MTOK / 4, 128>>>(x, norm1_g, norm1_b, act, 1);

    // 2) QKV GEMM -> fp16
    tgemm<3><<<dim3(3 * CH / 128, MTOK / 128), 256, TGEMM_SMEM>>>(
        act, qkvT, qkv_b, nullptr, qkv, MTOK, 3 * CH, CH);

    // 3) attention (HMMA)
    attn_kernel<<<BN * NHEAD, 256>>>(qkv, fusedb, act);

    // 4) proj GEMM -> fp16
    tgemm<3><<<dim3(CH / 128, MTOK / 128), 256, TGEMM_SMEM>>>(
        act, projT, proj_b, nullptr, projh, MTOK, CH, CH);

    // 5+6) reverse + residual -> d_out, fused LN2 (warp per token)
    fuse2_kernel<<<MTOK / 4, 128>>>(x, projh, norm2_g, norm2_b, out, act);

    // 7) FC1 + GELU -> fp16 hid
    tgemm<1><<<dim3(HID / 128, MTOK / 128), 256, TGEMM_SMEM>>>(
        act, fc1T, fc1_b, nullptr, hid, MTOK, HID, CH);

    // 8) FC2 + residual into d_out
    tgemm<2><<<dim3(CH / 128, MTOK / 128), 256, TGEMM_SMEM>>>(
        hid, fc2T, fc2_b, out, nullptr, MTOK, CH, HID);

    (void)in_sizes; (void)n_in; (void)out_size;
}

// round 14
// speedup vs baseline: 1.5079x; 1.0424x over previous
#include <cuda_runtime.h>
#include <cuda_fp16.h>
#include <math.h>
#include <stdint.h>

// ---------------- problem constants ----------------
#define BATCH   32
#define HIMG    56
#define WIMG    56
#define CH      512
#define NHEAD   16
#define WS      7
#define SSH     3
#define HD      32
#define NWIN    49
#define NW_IMG  64
#define BN      (BATCH*NW_IMG)      // 2048 windows
#define MTOK    (BN*NWIN)           // 100352 tokens
#define HID     2048
#define SCALE   0.17677669529663687f
#define NN      (NWIN*NWIN)         // 2401

// ---------------- scratch ----------------
__device__ __align__(128) unsigned char g_R1[(size_t)MTOK * HID * 4];
__device__ __align__(128) unsigned char g_R2[(size_t)MTOK * CH * 2];

__device__ __align__(128) __half g_qkvT[3 * CH * CH];
__device__ __align__(128) __half g_projT[CH * CH];
__device__ __align__(128) __half g_fc1T[HID * CH];
__device__ __align__(128) __half g_fc2T[CH * HID];

// ---------------- helpers ----------------
__device__ __forceinline__ uint32_t smem_u32(const void* p) {
    uint32_t a;
    asm("{ .reg .u64 t; cvta.to.shared.u64 t, %1; cvt.u32.u64 %0, t; }" : "=r"(a) : "l"(p));
    return a;
}
#define CP16(dst, src) \
    asm volatile("cp.async.cg.shared.global [%0], [%1], 16;" :: "r"(dst), "l"(src))
#define CPCOMMIT() asm volatile("cp.async.commit_group;" ::: "memory")
#define CPWAIT1()  asm volatile("cp.async.wait_group 1;" ::: "memory")
#define CPWAIT0()  asm volatile("cp.async.wait_group 0;" ::: "memory")

#define LDSM4(r, a) \
    asm volatile("ldmatrix.sync.aligned.m8n8.x4.shared.b16 {%0,%1,%2,%3}, [%4];" \
        : "=r"((r)[0]), "=r"((r)[1]), "=r"((r)[2]), "=r"((r)[3]) : "r"(a))

__device__ __forceinline__ void mma_f16(float* c, const uint32_t* a, const uint32_t* b) {
    asm volatile("mma.sync.aligned.m16n8k16.row.col.f32.f16.f16.f32 "
        "{%0,%1,%2,%3}, {%4,%5,%6,%7}, {%8,%9}, {%0,%1,%2,%3};"
        : "+f"(c[0]), "+f"(c[1]), "+f"(c[2]), "+f"(c[3])
        : "r"(a[0]), "r"(a[1]), "r"(a[2]), "r"(a[3]), "r"(b[0]), "r"(b[1]));
}

// ---------------- unified prep kernel ----------------
__device__ __forceinline__ void wsplit_tile(const float* __restrict__ W, __half* __restrict__ oh,
                                            int K, int N, int bx, int by, float (*t)[33])
{
    int n0 = bx * 32, k0 = by * 32;
    int tx = threadIdx.x & 31, ty = threadIdx.x >> 5;
    #pragma unroll
    for (int i = ty; i < 32; i += 8)
        t[i][tx] = W[(size_t)(k0 + i) * N + n0 + tx];
    __syncthreads();
    #pragma unroll
    for (int i = ty; i < 32; i += 8)
        oh[(size_t)(n0 + i) * K + k0 + tx] = __float2half_rn(t[tx][i]);
}

__global__ __launch_bounds__(256)
void prep_kernel(const float* __restrict__ qkv_w, const float* __restrict__ proj_w,
                 const float* __restrict__ fc1_w, const float* __restrict__ fc2_w,
                 __half* __restrict__ qkvT, __half* __restrict__ projT,
                 __half* __restrict__ fc1T, __half* __restrict__ fc2T,
                 const float* __restrict__ table, const int* __restrict__ relidx,
                 const float* __restrict__ mask, float* __restrict__ fusedb)
{
    __shared__ float t[32][33];
    int id = blockIdx.x;
    if (id < 768) {
        wsplit_tile(qkv_w, qkvT, CH, 3 * CH, id % 48, id / 48, t);
    } else if (id < 1024) {
        int s = id - 768;
        wsplit_tile(proj_w, projT, CH, CH, s % 16, s / 16, t);
    } else if (id < 2048) {
        int s = id - 1024;
        wsplit_tile(fc1_w, fc1T, CH, HID, s % 64, s / 64, t);
    } else if (id < 3072) {
        int s = id - 2048;
        wsplit_tile(fc2_w, fc2T, HID, CH, s % 16, s / 16, t);
    } else {
        int s = id - 3072;
        int wi = s >> 4, h = s & 15;
        float* dst = fusedb + (size_t)s * NN;
        const float* mrow = mask + (size_t)wi * NN;
        for (int i = threadIdx.x; i < NN; i += 256)
            dst[i] = table[relidx[i] * NHEAD + h] + mrow[i];
    }
}

// ---------------- LayerNorm, warp-per-token ----------------
__global__ __launch_bounds__(128)
void ln_kernel(const float* __restrict__ x, const float* __restrict__ gamma,
               const float* __restrict__ beta, __half* __restrict__ oh, int mode)
{
    int warp = threadIdx.x >> 5, lane = threadIdx.x & 31;
    int tok = blockIdx.x * 4 + warp;
    int src;
    if (mode == 1) {
        int w = tok / NWIN, n = tok - w * NWIN;
        int b = w >> 6, wi = w & 63;
        int wh = wi >> 3, ww = wi & 7;
        int i = n / WS, j = n - i * WS;
        int hp = wh * WS + i, wp = ww * WS + j;
        int hs = hp + SSH; if (hs >= HIMG) hs -= HIMG;
        int ws_ = wp + SSH; if (ws_ >= WIMG) ws_ -= WIMG;
        src = b * (HIMG * WIMG) + hs * WIMG + ws_;
    } else {
        src = tok;
    }
    const float* xp = x + (size_t)src * CH;
    float4 v[4];
    float s = 0.0f, sq = 0.0f;
    #pragma unroll
    for (int k = 0; k < 4; ++k) {
        v[k] = *(const float4*)(xp + k * 128 + lane * 4);
        s  += v[k].x + v[k].y + v[k].z + v[k].w;
        sq += v[k].x*v[k].x + v[k].y*v[k].y + v[k].z*v[k].z + v[k].w*v[k].w;
    }
    #pragma unroll
    for (int off = 16; off; off >>= 1) {
        s  += __shfl_xor_sync(0xffffffffu, s, off);
        sq += __shfl_xor_sync(0xffffffffu, sq, off);
    }
    float mean = s * (1.0f / CH);
    float inv = rsqrtf(sq * (1.0f / CH) - mean * mean + 1e-5f);
    __half* op = oh + (size_t)tok * CH;
    #pragma unroll
    for (int k = 0; k < 4; ++k) {
        int c = k * 128 + lane * 4;
        float4 g4 = *(const float4*)(gamma + c);
        float4 b4 = *(const float4*)(beta + c);
        __half hh[4];
        hh[0] = __float2half_rn((v[k].x - mean) * inv * g4.x + b4.x);
        hh[1] = __float2half_rn((v[k].y - mean) * inv * g4.y + b4.y);
        hh[2] = __float2half_rn((v[k].z - mean) * inv * g4.z + b4.z);
        hh[3] = __float2half_rn((v[k].w - mean) * inv * g4.w + b4.w);
        *(uint2*)(op + c) = *(uint2*)hh;
    }
}

// ---------------- fp16 GEMM via mma.sync (R9, f32 accumulate) ----------------
#define OFF_B   16384
#define STG_SZ  32768
#define TGEMM_SMEM (3 * STG_SZ)

template <int EPI>
__global__ void __launch_bounds__(256, 2)
tgemm(const __half* __restrict__ Ah, const __half* __restrict__ Bh,
      const float* __restrict__ bias, float* __restrict__ C,
      __half* __restrict__ Ch, int M, int N, int K)
{
    extern __shared__ __align__(128) char smem[];
    uint32_t sb = smem_u32(smem);
    int tid = threadIdx.x, wid = tid >> 5, lane = tid & 31;
    int m0 = blockIdx.y << 7, n0 = blockIdx.x << 7;
    int wm = wid & 3, wn = wid >> 2;

    int ar = tid >> 1, ac = (tid & 1) * 4;
    const char* gA = (const char*)(Ah + (size_t)(m0 + ar) * K) + ac * 16;
    const char* gB = (const char*)(Bh + (size_t)(n0 + ar) * K) + ac * 16;
    uint32_t sw[4];
    #pragma unroll
    for (int j = 0; j < 4; ++j)
        sw[j] = (uint32_t)(ar * 128 + (((ac + j) ^ (ar & 7)) << 4));

    int arow = wm * 32 + (lane & 15);
    uint32_t aterm = (uint32_t)(arow * 128);
    int axor = arow & 7;
    int ac16 = lane >> 4;
    int brow = wn * 64 + ((lane >> 4) & 1) * 8 + (lane & 7);
    uint32_t bterm = (uint32_t)(brow * 128);
    int bxor = brow & 7;
    int bc16 = (lane >> 3) & 1;

    float acc[2][8][4];
    #pragma unroll
    for (int i = 0; i < 2; ++i)
        #pragma unroll
        for (int j = 0; j < 8; ++j)
            #pragma unroll
            for (int q = 0; q < 4; ++q) acc[i][j][q] = 0.0f;

    const int nch = K >> 6;

    #pragma unroll
    for (int pc = 0; pc < 2; ++pc) {
        uint32_t s = sb + pc * STG_SZ;
        size_t go = (size_t)pc * 128;
        #pragma unroll
        for (int j = 0; j < 4; ++j) {
            CP16(s + sw[j],         gA + go + j * 16);
            CP16(s + OFF_B + sw[j], gB + go + j * 16);
        }
        CPCOMMIT();
    }

    int buf = 0;
    for (int c = 0; c < nch; ++c) {
        if (c + 1 < nch) { CPWAIT1(); } else { CPWAIT0(); }
        __syncthreads();
        if (c + 2 < nch) {
            int b2 = buf + 2; if (b2 >= 3) b2 -= 3;
            uint32_t s = sb + b2 * STG_SZ;
            size_t go = (size_t)(c + 2) * 128;
            #pragma unroll
            for (int j = 0; j < 4; ++j) {
                CP16(s + sw[j],         gA + go + j * 16);
                CP16(s + OFF_B + sw[j], gB + go + j * 16);
            }
            CPCOMMIT();
        } else {
            CPCOMMIT();
        }

        uint32_t sS = sb + buf * STG_SZ;
        #pragma unroll
        for (int k16 = 0; k16 < 4; ++k16) {
            uint32_t ah[2][4];
            uint32_t aoff = aterm + ((uint32_t)((2 * k16 + ac16) ^ axor) << 4);
            LDSM4(ah[0], sS + aoff);
            LDSM4(ah[1], sS + aoff + 2048);
            uint32_t boff = bterm + ((uint32_t)((2 * k16 + bc16) ^ bxor) << 4);
            #pragma unroll
            for (int ng = 0; ng < 4; ++ng) {
                uint32_t bh[4];
                LDSM4(bh, sS + OFF_B + boff + ng * 2048);
                #pragma unroll
                for (int mt = 0; mt < 2; ++mt) {
                    mma_f16(acc[mt][2 * ng],     ah[mt], &bh[0]);
                    mma_f16(acc[mt][2 * ng + 1], ah[mt], &bh[2]);
                }
            }
        }
        if (++buf == 3) buf = 0;
    }

    int r0 = m0 + wm * 32 + (lane >> 2);
    int cb = n0 + wn * 64 + (lane & 3) * 2;
    #pragma unroll
    for (int mt = 0; mt < 2; ++mt) {
        #pragma unroll
        for (int n8 = 0; n8 < 8; ++n8) {
            int col = cb + n8 * 8;
            float2 bv = *(const float2*)(bias + col);
            #pragma unroll
            for (int rt = 0; rt < 2; ++rt) {
                int row = r0 + mt * 16 + rt * 8;
                float vx = acc[mt][n8][rt * 2]     + bv.x;
                float vy = acc[mt][n8][rt * 2 + 1] + bv.y;
                if (EPI == 0) {
                    float2 r = {vx, vy};
                    *(float2*)(C + (size_t)row * N + col) = r;
                } else if (EPI == 1) {
                    float gx = 0.5f * vx * (1.0f + erff(vx * 0.70710678118654752f));
                    float gy = 0.5f * vy * (1.0f + erff(vy * 0.70710678118654752f));
                    __half hh[2];
                    hh[0] = __float2half_rn(gx);
                    hh[1] = __float2half_rn(gy);
                    *(uint32_t*)(Ch + (size_t)row * N + col) = *(uint32_t*)hh;
                } else if (EPI == 2) {
                    float* cp = C + (size_t)row * N + col;
                    float2 old = *(const float2*)cp;
                    float2 r = {vx + old.x, vy + old.y};
                    *(float2*)cp = r;
                } else {
                    __half hh[2];
                    hh[0] = __float2half_rn(vx);
                    hh[1] = __float2half_rn(vy);
                    *(uint32_t*)(Ch + (size_t)row * N + col) = *(uint32_t*)hh;
                }
            }
        }
    }
}

// ---------------- HMMA attention v3: register softmax, fragment repack ----------------
#define SQR 40   // q/k stride (halves)
#define SPR 72   // v^T stride (halves)
__global__ __launch_bounds__(256)
void attn_kernel(const __half* __restrict__ qkv, const float* __restrict__ fusedb,
                 __half* __restrict__ oh)
{
    __shared__ __half sq[64 * SQR], sk[64 * SQR], svt[32 * SPR];
    __shared__ float red[64][2][2];      // [row][wn][{max,sum}]
    __shared__ float pacc[4][16][34];    // partial O from wn=1 warps

    int bh = blockIdx.x;
    int b = bh >> 4, h = bh & 15;
    int tid = threadIdx.x, wid = tid >> 5, lane = tid & 31;
    const float* fb = fusedb + (size_t)(((b & 63) << 4) + h) * NN;

    // v^T padding cols m=49..63 -> 0
    for (int idx = tid; idx < 32 * 15; idx += 256) {
        int d = idx / 15, m = 49 + idx % 15;
        svt[d * SPR + m] = __float2half_rn(0.0f);
    }
    for (int idx = tid; idx < NWIN * 4; idx += 256) {
        int n = idx >> 2, c8 = (idx & 3) << 3;
        size_t base = (size_t)(b * NWIN + n) * (3 * CH) + h * HD + c8;
        *(uint4*)&sq[n * SQR + c8] = *(const uint4*)(qkv + base);
        *(uint4*)&sk[n * SQR + c8] = *(const uint4*)(qkv + base + CH);
    }
    for (int idx = tid; idx < NWIN * 16; idx += 256) {
        int m = idx >> 4, d = (idx & 15) * 2;
        __half2 v = *(const __half2*)(qkv + (size_t)(b * NWIN + m) * (3 * CH) + 2 * CH + h * HD + d);
        svt[d * SPR + m]       = __low2half(v);
        svt[(d + 1) * SPR + m] = __high2half(v);
    }
    __syncthreads();

    int wm = wid & 3, wn = wid >> 2;
    int r1 = wm * 16 + (lane >> 2), r2 = r1 + 8;

    // ---- S = Q @ K^T (per warp: rows 16, cols 32) ----
    float acc[4][4];
    #pragma unroll
    for (int f = 0; f < 4; ++f)
        #pragma unroll
        for (int q = 0; q < 4; ++q) acc[f][q] = 0.0f;
    {
        uint32_t aQ = smem_u32(sq) + (uint32_t)((wm * 16 + (lane & 15)) * (SQR * 2)) + (uint32_t)((lane >> 4) * 16);
        uint32_t bK = smem_u32(sk) + (uint32_t)((wn * 32 + ((lane >> 4) & 1) * 8 + (lane & 7)) * (SQR * 2))
                    + (uint32_t)(((lane >> 3) & 1) * 16);
        #pragma unroll
        for (int ks = 0; ks < 2; ++ks) {
            uint32_t af[4];
            LDSM4(af, aQ + ks * 32);
            #pragma unroll
            for (int half = 0; half < 2; ++half) {
                uint32_t bf[4];
                LDSM4(bf, bK + half * 16 * (SQR * 2) + ks * 32);
                mma_f16(acc[half * 2 + 0], af, &bf[0]);
                mma_f16(acc[half * 2 + 1], af, &bf[2]);
            }
        }
    }

    // ---- bias + mask into registers v[row][f*2+q] ----
    float v1r[8], v2r[8];
    #pragma unroll
    for (int f = 0; f < 4; ++f) {
        int c = wn * 32 + f * 8 + (lane & 3) * 2;
        bool c0 = c < NWIN, c1 = c + 1 < NWIN;
        bool rv1 = r1 < NWIN, rv2 = r2 < NWIN;
        v1r[f * 2]     = (rv1 && c0) ? acc[f][0] * SCALE + fb[r1 * NWIN + c]     : -1e30f;
        v1r[f * 2 + 1] = (rv1 && c1) ? acc[f][1] * SCALE + fb[r1 * NWIN + c + 1] : -1e30f;
        v2r[f * 2]     = (rv2 && c0) ? acc[f][2] * SCALE + fb[r2 * NWIN + c]     : -1e30f;
        v2r[f * 2 + 1] = (rv2 && c1) ? acc[f][3] * SCALE + fb[r2 * NWIN + c + 1] : -1e30f;
    }

    // ---- per-warp partial softmax (max + sum of exp over own 32 cols) ----
    float m1 = -1e30f, m2 = -1e30f;
    #pragma unroll
    for (int j = 0; j < 8; ++j) { m1 = fmaxf(m1, v1r[j]); m2 = fmaxf(m2, v2r[j]); }
    m1 = fmaxf(m1, __shfl_xor_sync(0xffffffffu, m1, 1));
    m1 = fmaxf(m1, __shfl_xor_sync(0xffffffffu, m1, 2));
    m2 = fmaxf(m2, __shfl_xor_sync(0xffffffffu, m2, 1));
    m2 = fmaxf(m2, __shfl_xor_sync(0xffffffffu, m2, 2));
    float s1 = 0.0f, s2 = 0.0f;
    #pragma unroll
    for (int j = 0; j < 8; ++j) {
        v1r[j] = expf(v1r[j] - m1); s1 += v1r[j];
        v2r[j] = expf(v2r[j] - m2); s2 += v2r[j];
    }
    s1 += __shfl_xor_sync(0xffffffffu, s1, 1);
    s1 += __shfl_xor_sync(0xffffffffu, s1, 2);
    s2 += __shfl_xor_sync(0xffffffffu, s2, 1);
    s2 += __shfl_xor_sync(0xffffffffu, s2, 2);
    if ((lane & 3) == 0) {
        red[r1][wn][0] = m1; red[r1][wn][1] = s1;
        red[r2][wn][0] = m2; red[r2][wn][1] = s2;
    }
    __syncthreads();

    // ---- combine across the two wn warps ----
    float M1 = fmaxf(red[r1][0][0], red[r1][1][0]);
    float S1 = red[r1][0][1] * expf(red[r1][0][0] - M1) + red[r1][1][1] * expf(red[r1][1][0] - M1);
    float fac1 = expf(m1 - M1) / S1;
    float M2 = fmaxf(red[r2][0][0], red[r2][1][0]);
    float S2 = red[r2][0][1] * expf(red[r2][0][0] - M2) + red[r2][1][1] * expf(red[r2][1][0] - M2);
    float fac2 = expf(m2 - M2) / S2;

    // ---- O_partial = P(own 32 k) @ V, P packed straight from registers ----
    float acc2[4][4];
    #pragma unroll
    for (int nt = 0; nt < 4; ++nt)
        #pragma unroll
        for (int q = 0; q < 4; ++q) acc2[nt][q] = 0.0f;
    {
        uint32_t vb = smem_u32(svt);
        #pragma unroll
        for (int t = 0; t < 2; ++t) {
            uint32_t ap[4];
            __half2 h0 = __floats2half2_rn(v1r[4 * t]     * fac1, v1r[4 * t + 1] * fac1);
            __half2 h1 = __floats2half2_rn(v2r[4 * t]     * fac2, v2r[4 * t + 1] * fac2);
            __half2 h2 = __floats2half2_rn(v1r[4 * t + 2] * fac1, v1r[4 * t + 3] * fac1);
            __half2 h3 = __floats2half2_rn(v2r[4 * t + 2] * fac2, v2r[4 * t + 3] * fac2);
            ap[0] = *(uint32_t*)&h0; ap[1] = *(uint32_t*)&h1;
            ap[2] = *(uint32_t*)&h2; ap[3] = *(uint32_t*)&h3;
            #pragma unroll
            for (int dt = 0; dt < 2; ++dt) {
                uint32_t bf[4];
                uint32_t addr = vb + (uint32_t)((dt * 16 + ((lane >> 4) & 1) * 8 + (lane & 7)) * (SPR * 2))
                              + (uint32_t)(((lane >> 3) & 1) * 16) + (uint32_t)(wn * 64 + t * 32);
                LDSM4(bf, addr);
                mma_f16(acc2[dt * 2 + 0], ap, &bf[0]);
                mma_f16(acc2[dt * 2 + 1], ap, &bf[2]);
            }
        }
    }

    // ---- cross-warp partial-O sum; wn=1 writes, wn=0 adds + stores ----
    if (wn == 1) {
        #pragma unroll
        for (int nt = 0; nt < 4; ++nt) {
            int d = nt * 8 + (lane & 3) * 2;
            *(float2*)&pacc[wm][lane >> 2][d]       = make_float2(acc2[nt][0], acc2[nt][1]);
            *(float2*)&pacc[wm][(lane >> 2) + 8][d] = make_float2(acc2[nt][2], acc2[nt][3]);
        }
    }
    __syncthreads();
    if (wn == 0) {
        #pragma unroll
        for (int nt = 0; nt < 4; ++nt) {
            int d = nt * 8 + (lane & 3) * 2;
            float2 p1 = *(const float2*)&pacc[wm][lane >> 2][d];
            float2 p2 = *(const float2*)&pacc[wm][(lane >> 2) + 8][d];
            if (r1 < NWIN)
                *(__half2*)(oh + (size_t)(b * NWIN + r1) * CH + h * HD + d) =
                    __floats2half2_rn(acc2[nt][0] + p1.x, acc2[nt][1] + p1.y);
            if (r2 < NWIN)
                *(__half2*)(oh + (size_t)(b * NWIN + r2) * CH + h * HD + d) =
                    __floats2half2_rn(acc2[nt][2] + p2.x, acc2[nt][3] + p2.y);
        }
    }
}

// ---------------- fused: reverse+roll+residual -> out, LN2 -> yh (warp/token) ----------------
__global__ __launch_bounds__(128)
void fuse2_kernel(const float* __restrict__ x, const __half* __restrict__ projh,
                  const float* __restrict__ gamma, const float* __restrict__ beta,
                  float* __restrict__ out, __half* __restrict__ yh)
{
    int warp = threadIdx.x >> 5, lane = threadIdx.x & 31;
    int tok = blockIdx.x * 4 + warp;
    int b = tok / (HIMG * WIMG);
    int rem = tok - b * (HIMG * WIMG);
    int hp0 = rem / WIMG, wp0 = rem - hp0 * WIMG;
    int hp = hp0 - SSH; if (hp < 0) hp += HIMG;
    int wp = wp0 - SSH; if (wp < 0) wp += WIMG;
    int wh = hp / WS, i = hp - wh * WS;
    int ww = wp / WS, j = wp - ww * WS;
    int src = (b * NW_IMG + wh * 8 + ww) * NWIN + i * WS + j;

    const float* xp = x + (size_t)tok * CH;
    const __half* pp = projh + (size_t)src * CH;
    float* op = out + (size_t)tok * CH;

    float4 a[4];
    float s = 0.0f, sq = 0.0f;
    #pragma unroll
    for (int k = 0; k < 4; ++k) {
        int c = k * 128 + lane * 4;
        a[k] = *(const float4*)(xp + c);
        union { uint2 u; __half hx[4]; } ph;
        ph.u = *(const uint2*)(pp + c);
        a[k].x += __half2float(ph.hx[0]);
        a[k].y += __half2float(ph.hx[1]);
        a[k].z += __half2float(ph.hx[2]);
        a[k].w += __half2float(ph.hx[3]);
        *(float4*)(op + c) = a[k];
        s  += a[k].x + a[k].y + a[k].z + a[k].w;
        sq += a[k].x*a[k].x + a[k].y*a[k].y + a[k].z*a[k].z + a[k].w*a[k].w;
    }
    #pragma unroll
    for (int off = 16; off; off >>= 1) {
        s  += __shfl_xor_sync(0xffffffffu, s, off);
        sq += __shfl_xor_sync(0xffffffffu, sq, off);
    }
    float mean = s * (1.0f / CH);
    float inv = rsqrtf(sq * (1.0f / CH) - mean * mean + 1e-5f);
    __half* yp = yh + (size_t)tok * CH;
    #pragma unroll
    for (int k = 0; k < 4; ++k) {
        int c = k * 128 + lane * 4;
        float4 g4 = *(const float4*)(gamma + c);
        float4 b4 = *(const float4*)(beta + c);
        __half hh[4];
        hh[0] = __float2half_rn((a[k].x - mean) * inv * g4.x + b4.x);
        hh[1] = __float2half_rn((a[k].y - mean) * inv * g4.y + b4.y);
        hh[2] = __float2half_rn((a[k].z - mean) * inv * g4.z + b4.z);
        hh[3] = __float2half_rn((a[k].w - mean) * inv * g4.w + b4.w);
        *(uint2*)(yp + c) = *(uint2*)hh;
    }
}

// ---------------- launcher ----------------
extern "C" void kernel_launch(void* const* d_in, const int* in_sizes, int n_in,
                              void* d_out, int out_size)
{
    const float* x        = (const float*)d_in[0];
    const float* norm1_g  = (const float*)d_in[1];
    const float* norm1_b  = (const float*)d_in[2];
    const float* qkv_w    = (const float*)d_in[3];
    const float* qkv_b    = (const float*)d_in[4];
    const float* rel_tab  = (const float*)d_in[5];
    const float* proj_w   = (const float*)d_in[6];
    const float* proj_b   = (const float*)d_in[7];
    const float* norm2_g  = (const float*)d_in[8];
    const float* norm2_b  = (const float*)d_in[9];
    const float* fc1_w    = (const float*)d_in[10];
    const float* fc1_b    = (const float*)d_in[11];
    const float* fc2_w    = (const float*)d_in[12];
    const float* fc2_b    = (const float*)d_in[13];
    const int*   rel_idx  = (const int*)d_in[14];
    const float* attn_msk = (const float*)d_in[15];
    float* out = (float*)d_out;

    unsigned char *R1, *R2;
    cudaGetSymbolAddress((void**)&R1, g_R1);
    cudaGetSymbolAddress((void**)&R2, g_R2);
    __half *qkvT, *projT, *fc1T, *fc2T;
    cudaGetSymbolAddress((void**)&qkvT, g_qkvT);
    cudaGetSymbolAddress((void**)&projT, g_projT);
    cudaGetSymbolAddress((void**)&fc1T, g_fc1T);
    cudaGetSymbolAddress((void**)&fc2T, g_fc2T);

    __half* qkv   = (__half*)R1;
    __half* projh = (__half*)(R1 + (size_t)MTOK * 3 * CH * 2);
    float* fusedb = (float*)(R1 + (size_t)600 * 1024 * 1024);
    __half* hid   = (__half*)R1;
    __half* act   = (__half*)R2;

    cudaFuncSetAttribute(tgemm<0>, cudaFuncAttributeMaxDynamicSharedMemorySize, TGEMM_SMEM);
    cudaFuncSetAttribute(tgemm<1>, cudaFuncAttributeMaxDynamicSharedMemorySize, TGEMM_SMEM);
    cudaFuncSetAttribute(tgemm<2>, cudaFuncAttributeMaxDynamicSharedMemorySize, TGEMM_SMEM);
    cudaFuncSetAttribute(tgemm<3>, cudaFuncAttributeMaxDynamicSharedMemorySize, TGEMM_SMEM);

    // 0) unified prep
    prep_kernel<<<4096, 256>>>(qkv_w, proj_w, fc1_w, fc2_w, qkvT, projT, fc1T, fc2T,
                               rel_tab, rel_idx, attn_msk, fusedb);

    // 1) LN1 + shift + window partition
    ln_kernel<<<MTOK / 4, 128>>>(x, norm1_g, norm1_b, act, 1);

    // 2) QKV GEMM -> fp16
    tgemm<3><<<dim3(3 * CH / 128, MTOK / 128), 256, TGEMM_SMEM>>>(
        act, qkvT, qkv_b, nullptr, qkv, MTOK, 3 * CH, CH);

    // 3) attention (HMMA, register softmax)
    attn_kernel<<<BN * NHEAD, 256>>>(qkv, fusedb, act);

    // 4) proj GEMM -> fp16
    tgemm<3><<<dim3(CH / 128, MTOK / 128), 256, TGEMM_SMEM>>>(
        act, projT, proj_b, nullptr, projh, MTOK, CH, CH);

    // 5+6) reverse + residual -> d_out, fused LN2
    fuse2_kernel<<<MTOK / 4, 128>>>(x, projh, norm2_g, norm2_b, out, act);

    // 7) FC1 + GELU -> fp16 hid
    tgemm<1><<<dim3(HID / 128, MTOK / 128), 256, TGEMM_SMEM>>>(
        act, fc1T, fc1_b, nullptr, hid, MTOK, HID, CH);

    // 8) FC2 + residual into d_out
    tgemm<2><<<dim3(CH / 128, MTOK / 128), 256, TGEMM_SMEM>>>(
        hid, fc2T, fc2_b, out, nullptr, MTOK, CH, HID);

    (void)in_sizes; (void)n_in; (void)out_size;
}